// round 15
// baseline (speedup 1.0000x reference)
#include <cuda_runtime.h>
#include <cuda_bf16.h>
#include <cstdint>

#define N_NODES 10000
#define N_EDGES 320000
#define MROWS 10176
#define NBY 70                // ceil(10000/144)
#define TOTAL_CTAS 140        // 2 * 70
#define HSIZE (1 << 20)
#define HMASK (HSIZE - 1)

// ---------------- scratch (static device globals; no allocation) ----------------
__device__ unsigned int g_htab[HSIZE];
__device__ float g_deg[N_NODES];
__device__ float g_psum[NBY * 256];
__device__ float g_psum2[NBY * 256];
__device__ float g_mean[256];
__device__ float g_rstd[256];
__device__ float g_u1[256];
__device__ float g_bias0p[128];
__device__ unsigned int g_ctr;
__device__ unsigned int g_flag;
__device__ int g_is64;
// bf16-split activations, zero-padded rows to MROWS (padding stays zero forever)
__device__ __nv_bfloat16 g_a1h[MROWS * 256];
__device__ __nv_bfloat16 g_a1l[MROWS * 256];
__device__ __nv_bfloat16 g_a2h[MROWS * 256];
__device__ __nv_bfloat16 g_a2l[MROWS * 256];
// transposed + bf16-split weights, zero-padded: [Npad][KP]
__device__ __nv_bfloat16 g_wth0[256 * 512];
__device__ __nv_bfloat16 g_wtl0[256 * 512];
__device__ __nv_bfloat16 g_wth1[256 * 256];    // BN0-scaled (folded in conv0 tail)
__device__ __nv_bfloat16 g_wtl1[256 * 256];
__device__ __nv_bfloat16 g_wth2[128 * 256];    // BN1-scaled (folded in conv1 tail)
__device__ __nv_bfloat16 g_wtl2[128 * 256];
__device__ __nv_bfloat16 g_wth3[128 * 128];
__device__ __nv_bfloat16 g_wtl3[128 * 128];

// ---------------- helpers ----------------
__device__ __forceinline__ uint32_t s2u(const void* p) {
    uint32_t a;
    asm("{ .reg .u64 t; cvta.to.shared.u64 t, %1; cvt.u32.u64 %0, t; }" : "=r"(a) : "l"(p));
    return a;
}

__device__ __forceinline__ void bsplit(float v, unsigned short& h, unsigned short& l) {
    __nv_bfloat16 hb = __float2bfloat16(v);
    float r = v - __bfloat162float(hb);
    __nv_bfloat16 lb = __float2bfloat16(r);
    h = __bfloat16_as_ushort(hb);
    l = __bfloat16_as_ushort(lb);
}

#define LDX4(r, addr) \
    asm volatile("ldmatrix.sync.aligned.m8n8.x4.shared.b16 {%0,%1,%2,%3}, [%4];" \
                 : "=r"((r)[0]), "=r"((r)[1]), "=r"((r)[2]), "=r"((r)[3]) : "r"(addr))

#define MMA(d, a, b0, b1) \
    asm volatile("mma.sync.aligned.m16n8k16.row.col.f32.bf16.bf16.f32 " \
                 "{%0,%1,%2,%3}, {%4,%5,%6,%7}, {%8,%9}, {%0,%1,%2,%3};" \
                 : "+f"((d)[0]), "+f"((d)[1]), "+f"((d)[2]), "+f"((d)[3]) \
                 : "r"((a)[0]), "r"((a)[1]), "r"((a)[2]), "r"((a)[3]), "r"(b0), "r"(b1))

#define CP_ASYNC16(dst, src) \
    asm volatile("cp.async.cg.shared.global [%0], [%1], 16;" :: "r"(dst), "l"(src))

// ---------------- prep: W0/fW1 transposes + hash init + deg init + detect ----------------
// [0,144) transpose, [144,1168) htab, [1168,1208) deg/detect
__global__ void prep_kernel(const float* __restrict__ W0, const float* __restrict__ fW1,
                            const unsigned int* __restrict__ eiw) {
    int b = blockIdx.x, tid = threadIdx.x;
    if (b < 144) {
        const float* W;
        __nv_bfloat16 *th, *tl;
        int K, KP, N, nk, lb;
        if (b < 128) { W = W0;  th = g_wth0; tl = g_wtl0; K = 500; KP = 512; N = 256; nk = 16; lb = b; }
        else         { W = fW1; th = g_wth3; tl = g_wtl3; K = 128; KP = 128; N = 40;  nk = 4;  lb = b - 128; }
        int k0 = (lb % nk) * 32, n0 = (lb / nk) * 32;
        __shared__ float t[32][33];
        int tx = tid & 31, ty = tid >> 5;
        for (int dy = ty; dy < 32; dy += 8) {
            int k = k0 + dy, n = n0 + tx;
            t[dy][tx] = (k < K && n < N) ? W[(size_t)k * N + n] : 0.f;
        }
        __syncthreads();
        for (int dy = ty; dy < 32; dy += 8) {
            int n = n0 + dy, k = k0 + tx;
            unsigned short h, l;
            bsplit(t[tx][dy], h, l);
            th[(size_t)n * KP + k] = __ushort_as_bfloat16(h);
            tl[(size_t)n * KP + k] = __ushort_as_bfloat16(l);
        }
    } else if (b < 1168) {
        int i = (b - 144) * 256 + tid;
        uint4 ff = {~0u, ~0u, ~0u, ~0u};
        *(uint4*)&g_htab[i * 4] = ff;
    } else {
        int lb = b - 1168;
        int i = lb * 256 + tid;
        if (i < N_NODES) g_deg[i] = 1.0f;
        if (lb == 0 && tid < 32) {
            unsigned bad = (eiw[2 * tid + 1] != 0u) ? 1u : 0u;
            unsigned m = __ballot_sync(0xffffffffu, bad);
            if (tid == 0) {
                g_is64 = (m == 0) ? 1 : 0;
                g_flag = 0u;
                g_ctr = 0u;
            }
        }
    }
}

// ---------------- degree with hash-set dedup, 2 edges/thread ----------------
__global__ void deg_kernel(const void* __restrict__ ei_raw) {
    int t = blockIdx.x * blockDim.x + threadIdx.x;
    const int half = N_EDGES / 2;
    if (t >= half) return;
    const int is64 = g_is64;
#pragma unroll
    for (int u = 0; u < 2; u++) {
        int e = t + u * half;
        int s, d;
        if (is64) {
            const long long* p = (const long long*)ei_raw;
            s = (int)p[e];
            d = (int)p[e + N_EDGES];
        } else {
            const int* p = (const int*)ei_raw;
            s = p[e];
            d = p[e + N_EDGES];
        }
        if ((unsigned)s >= N_NODES || (unsigned)d >= N_NODES) continue;
        if (s == d) continue;
        unsigned int k = (unsigned int)s * (unsigned int)N_NODES + (unsigned int)d;
        unsigned int h = (k * 2654435761u) >> 12;
        for (unsigned int j = 0;; j++) {
            unsigned int slot = (h + j) & HMASK;
            unsigned int old = atomicCAS(&g_htab[slot], 0xFFFFFFFFu, k);
            if (old == 0xFFFFFFFFu) { atomicAdd(&g_deg[s], 1.0f); break; }
            if (old == k) break;
        }
    }
}

// ---------------- conv GEMM: BM=144, BN=128, BK=32, 384 threads (12 warps 3m x 4n) --------
// FP32A: A loaded fp32 via cp.async staging, split to bf16 hi/lo in smem in-pipeline.
// SPLIT: A pre-split bf16 hi/lo in global (conv1 path).
#define ROWB 80
// SPLIT layout
#define GA_H 0
#define GA_L 11520
#define GB_H 23040
#define GB_L 33280
#define GBUF 43520
#define GSMEM_S (3 * GBUF + 1024)
// FP32A layout: B bufs [0,61440), SF fp32 [61440,123648), A bf16 [123648,169728)
#define F_BBUF 20480
#define F_SF 61440
#define F_SFBUF 20736
#define F_AB 123648
#define F_ABBUF 23040
#define GSMEM_F (169728 + 1024)

template <bool FP32A>
__global__ void __launch_bounds__(384, 1)
gemm144(const float* __restrict__ Af,
        const __nv_bfloat16* __restrict__ Ah, const __nv_bfloat16* __restrict__ Al,
        const __nv_bfloat16* __restrict__ Bh, const __nv_bfloat16* __restrict__ Bl,
        const float* __restrict__ bias, const float* __restrict__ prebias,
        const float* __restrict__ rs,
        __nv_bfloat16* __restrict__ Ch, __nv_bfloat16* __restrict__ Cl,
        int M, int Kreal, int Kpad,
        const float* __restrict__ Wn, const float* __restrict__ gamn,
        const float* __restrict__ betn,
        __nv_bfloat16* __restrict__ tho, __nv_bfloat16* __restrict__ tlo,
        float* __restrict__ uo, const float* __restrict__ extran,
        int Nn, unsigned int gen) {
    extern __shared__ char smraw[];
    uint32_t raw = s2u(smraw);
    uint32_t sbase = (raw + 1023u) & ~1023u;
    char* sb = smraw + (sbase - raw);

    const int tid = threadIdx.x, lane = tid & 31, wid = tid >> 5;
    const int row0 = blockIdx.y * 144, col0 = blockIdx.x * 128;
    const int wm = (wid >> 2) * 48, wn = (wid & 3) * 32;
    const int nch = Kpad >> 5;
    const int Ncols = 256;

    float acc[3][4][4];
#pragma unroll
    for (int i = 0; i < 3; i++)
#pragma unroll
        for (int j = 0; j < 4; j++)
#pragma unroll
            for (int c = 0; c < 4; c++) acc[i][j][c] = 0.f;

    const uint32_t a_lo = (uint32_t)((lane & 15) * ROWB + ((lane >> 4) & 1) * 16);
    const uint32_t b_lo = (uint32_t)((lane & 7) * ROWB + ((lane & 16) ? 8 * ROWB : 0) +
                                     ((lane & 8) ? 16 : 0));

    auto prefetch = [&](int ch) {
        const int k0 = ch << 5;
        if (FP32A) {
            const uint32_t bb = sbase + (ch % 3) * F_BBUF;
            for (int idx = tid; idx < 512; idx += 384) {
                int r = idx >> 2, q = idx & 3;
                size_t bo = (size_t)(col0 + r) * Kpad + k0 + q * 8;
                uint32_t so = (uint32_t)(r * ROWB + q * 16);
                CP_ASYNC16(bb + so, (const void*)(Bh + bo));
                CP_ASYNC16(bb + 10240 + so, (const void*)(Bl + bo));
            }
            const uint32_t sf = sbase + F_SF + (ch % 3) * F_SFBUF;
            for (int idx = tid; idx < 1152; idx += 384) {  // 144 rows x 8 x 16B (4 floats)
                int r = idx >> 3, q = idx & 7;
                int gr = row0 + r, c4 = k0 + q * 4;
                uint32_t dst = sf + (uint32_t)(r * 144 + q * 16);
                if (gr < M && c4 + 4 <= Kreal) {
                    CP_ASYNC16(dst, (const void*)(Af + (size_t)gr * Kreal + c4));
                } else {
                    asm volatile("st.shared.v4.b32 [%0], {%1,%1,%1,%1};"
                                 :: "r"(dst), "r"(0) : "memory");
                }
            }
        } else {
            const uint32_t bu = sbase + (ch % 3) * GBUF;
            for (int idx = tid; idx < 576; idx += 384) {
                int r = idx >> 2, q = idx & 3;
                size_t ao = (size_t)(row0 + r) * Kpad + k0 + q * 8;
                uint32_t so = (uint32_t)(r * ROWB + q * 16);
                CP_ASYNC16(bu + GA_H + so, (const void*)(Ah + ao));
                CP_ASYNC16(bu + GA_L + so, (const void*)(Al + ao));
            }
            for (int idx = tid; idx < 512; idx += 384) {
                int r = idx >> 2, q = idx & 3;
                size_t bo = (size_t)(col0 + r) * Kpad + k0 + q * 8;
                uint32_t so = (uint32_t)(r * ROWB + q * 16);
                CP_ASYNC16(bu + GB_H + so, (const void*)(Bh + bo));
                CP_ASYNC16(bu + GB_L + so, (const void*)(Bl + bo));
            }
        }
        asm volatile("cp.async.commit_group;" ::: "memory");
    };

    prefetch(0);
    prefetch(1);

    for (int ch = 0; ch < nch; ch++) {
        if (ch + 1 < nch) { asm volatile("cp.async.wait_group 1;" ::: "memory"); }
        else              { asm volatile("cp.async.wait_group 0;" ::: "memory"); }
        __syncthreads();
        if (ch + 2 < nch) prefetch(ch + 2);

        uint32_t aBase, bBase;
        if (FP32A) {
            // convert fp32 staging -> bf16 hi/lo (12 elems/thread)
            const uint32_t sf = sbase + F_SF + (ch % 3) * F_SFBUF;
            const uint32_t ab = sbase + F_AB + (ch & 1) * F_ABBUF;
#pragma unroll
            for (int t = 0; t < 12; t++) {
                int idx = tid + t * 384;     // 0..4607: 144 rows x 32 cols
                int r = idx >> 5, c = idx & 31;
                float v;
                asm("ld.shared.f32 %0, [%1];" : "=f"(v) : "r"(sf + r * 144 + c * 4));
                unsigned short h, l;
                bsplit(v, h, l);
                asm volatile("st.shared.u16 [%0], %1;"
                             :: "r"(ab + (uint32_t)(r * ROWB + c * 2)), "h"(h) : "memory");
                asm volatile("st.shared.u16 [%0], %1;"
                             :: "r"(ab + 11520u + (uint32_t)(r * ROWB + c * 2)), "h"(l) : "memory");
            }
            __syncthreads();
            aBase = ab;
            bBase = sbase + (ch % 3) * F_BBUF;
        } else {
            aBase = sbase + (ch % 3) * GBUF + GA_H;
            bBase = sbase + (ch % 3) * GBUF + GB_H;
        }
        const uint32_t aLoOff = 11520, bLoOff = 10240;

#pragma unroll
        for (int ks = 0; ks < 2; ks++) {
            uint32_t ah[3][4], al[3][4];
#pragma unroll
            for (int mt = 0; mt < 3; mt++) {
                uint32_t ka = aBase + (uint32_t)((wm + mt * 16) * ROWB) + a_lo + ks * 32;
                LDX4(ah[mt], ka);
                LDX4(al[mt], ka + aLoOff);
            }
#pragma unroll
            for (int nt = 0; nt < 2; nt++) {
                uint32_t kb = bBase + (uint32_t)((wn + nt * 16) * ROWB) + b_lo + ks * 32;
                uint32_t bh[4], bl[4];
                LDX4(bh, kb);
                LDX4(bl, kb + bLoOff);
#pragma unroll
                for (int mt = 0; mt < 3; mt++) {
                    MMA(acc[mt][nt * 2 + 0], ah[mt], bh[0], bh[1]);
                    MMA(acc[mt][nt * 2 + 1], ah[mt], bh[2], bh[3]);
                    MMA(acc[mt][nt * 2 + 0], al[mt], bh[0], bh[1]);
                    MMA(acc[mt][nt * 2 + 1], al[mt], bh[2], bh[3]);
                    MMA(acc[mt][nt * 2 + 0], ah[mt], bl[0], bl[1]);
                    MMA(acc[mt][nt * 2 + 1], ah[mt], bl[2], bl[3]);
                }
            }
        }
        __syncthreads();
    }

    // epilogue: v = relu(rs*(acc + u) + bias); bf16-split stores + fused column stats
    float ts[4][2], ts2[4][2];
#pragma unroll
    for (int j = 0; j < 4; j++) { ts[j][0] = ts[j][1] = ts2[j][0] = ts2[j][1] = 0.f; }
#pragma unroll
    for (int mi = 0; mi < 3; mi++) {
        int r0_ = row0 + wm + mi * 16 + (lane >> 2);
        bool ok0 = r0_ < M, ok1 = (r0_ + 8) < M;
        float d0 = 1.f, d1 = 1.f;
        if (rs) {
            if (ok0) d0 = rs[r0_];
            if (ok1) d1 = rs[r0_ + 8];
        }
#pragma unroll
        for (int j = 0; j < 4; j++) {
            int gc = col0 + wn + (j >> 1) * 16 + (j & 1) * 8 + (lane & 3) * 2;
            float bv0 = bias[gc], bv1 = bias[gc + 1];
            float u0 = prebias ? prebias[gc] : 0.f;
            float u1 = prebias ? prebias[gc + 1] : 0.f;
            float v0 = d0 * (acc[mi][j][0] + u0) + bv0; v0 = v0 > 0.f ? v0 : 0.f;
            float v1 = d0 * (acc[mi][j][1] + u1) + bv1; v1 = v1 > 0.f ? v1 : 0.f;
            float v2 = d1 * (acc[mi][j][2] + u0) + bv0; v2 = v2 > 0.f ? v2 : 0.f;
            float v3 = d1 * (acc[mi][j][3] + u1) + bv1; v3 = v3 > 0.f ? v3 : 0.f;
            if (ok0) { ts[j][0] += v0; ts2[j][0] += v0 * v0;
                       ts[j][1] += v1; ts2[j][1] += v1 * v1; }
            if (ok1) { ts[j][0] += v2; ts2[j][0] += v2 * v2;
                       ts[j][1] += v3; ts2[j][1] += v3 * v3; }
            unsigned short h0, h1_, h2_, h3_, l0, l1_, l2_, l3_;
            bsplit(v0, h0, l0); bsplit(v1, h1_, l1_);
            bsplit(v2, h2_, l2_); bsplit(v3, h3_, l3_);
            if (ok0) {
                *(uint32_t*)&Ch[(size_t)r0_ * Ncols + gc] = (uint32_t)h0 | ((uint32_t)h1_ << 16);
                *(uint32_t*)&Cl[(size_t)r0_ * Ncols + gc] = (uint32_t)l0 | ((uint32_t)l1_ << 16);
            }
            if (ok1) {
                *(uint32_t*)&Ch[(size_t)(r0_ + 8) * Ncols + gc] = (uint32_t)h2_ | ((uint32_t)h3_ << 16);
                *(uint32_t*)&Cl[(size_t)(r0_ + 8) * Ncols + gc] = (uint32_t)l2_ | ((uint32_t)l3_ << 16);
            }
        }
    }

    // warp-level stat reduce
#pragma unroll
    for (int j = 0; j < 4; j++)
#pragma unroll
        for (int k = 0; k < 2; k++) {
#pragma unroll
            for (int off = 4; off < 32; off <<= 1) {
                ts[j][k] += __shfl_xor_sync(0xffffffffu, ts[j][k], off);
                ts2[j][k] += __shfl_xor_sync(0xffffffffu, ts2[j][k], off);
            }
        }
    float* sS = (float*)sb;                 // [12][32]
    float* sS2 = sS + 12 * 32;
    __syncthreads();
    if (lane < 4) {
#pragma unroll
        for (int j = 0; j < 4; j++) {
            int cloc = (j >> 1) * 16 + (j & 1) * 8 + lane * 2;
            sS[wid * 32 + cloc] = ts[j][0];
            sS[wid * 32 + cloc + 1] = ts[j][1];
            sS2[wid * 32 + cloc] = ts2[j][0];
            sS2[wid * 32 + cloc + 1] = ts2[j][1];
        }
    }
    __syncthreads();
    if (tid < 128) {
        int c = tid;
        int g = c >> 5, cloc = c & 31;
        float s = 0.f, s2 = 0.f;
#pragma unroll
        for (int w = 0; w < 3; w++) {
            s += sS[(g + 4 * w) * 32 + cloc];
            s2 += sS2[(g + 4 * w) * 32 + cloc];
        }
        g_psum[blockIdx.y * 256 + col0 + c] = s;
        g_psum2[blockIdx.y * 256 + col0 + c] = s2;
        __threadfence();
    }
    __syncthreads();

    // ---- grid-resident handoff: last CTA finalizes stats + releases flag ----
    __shared__ int s_last;
    if (tid == 0) {
        unsigned int o = atomicAdd(&g_ctr, 1u);
        s_last = (o == TOTAL_CTAS - 1) ? 1 : 0;
    }
    __syncthreads();
    if (s_last) {
        __threadfence();
        if (tid < 256) {
            int c = tid;
            float s = 0.f, s2 = 0.f;
            for (int b = 0; b < NBY; b++) { s += g_psum[b * 256 + c]; s2 += g_psum2[b * 256 + c]; }
            float m = s / (float)M;
            float var = s2 / (float)M - m * m;
            g_mean[c] = m;
            g_rstd[c] = rsqrtf(var + 1e-5f);
        }
        if (tid == 0) g_ctr = 0;
        __threadfence();
        __syncthreads();
        if (tid == 0) atomicExch(&g_flag, gen);
    } else {
        if (tid == 0) {
            while (atomicAdd(&g_flag, 0u) < gen) __nanosleep(64);
        }
        __syncthreads();
        __threadfence();
    }

    // ---- cooperative BN fold ----
    {
        const int Kn = 256, ntk = 8;
        int ntiles = ntk * (Nn >> 5);
        int ngemv = Nn >> 5;
        int unit = blockIdx.y * 2 + blockIdx.x;   // 0..139
        if (unit < ntiles) {
            __shared__ float t[32][33];
            __shared__ float ss[32];
            int k0 = (unit % ntk) * 32, n0 = (unit / ntk) * 32;
            int tx = tid & 31, ty = tid >> 5;
            if (tid < 32) ss[tid] = g_rstd[k0 + tid] * gamn[k0 + tid];
            for (int dy = ty; dy < 32; dy += 12)
                t[dy][tx] = Wn[(size_t)(k0 + dy) * Nn + n0 + tx];
            __syncthreads();
            for (int dy = ty; dy < 32; dy += 12) {
                int n = n0 + dy, k = k0 + tx;
                unsigned short h, l;
                bsplit(t[tx][dy] * ss[tx], h, l);
                tho[(size_t)n * Kn + k] = __ushort_as_bfloat16(h);
                tlo[(size_t)n * Kn + k] = __ushort_as_bfloat16(l);
            }
        } else if (unit < ntiles + ngemv) {
            int n0 = (unit - ntiles) * 32;
            int tx = tid & 31, ty = tid >> 5;
            __shared__ float tsv[256];
            __shared__ float red[8][33];
            if (tid < 256) {
                float s = g_rstd[tid] * gamn[tid];
                tsv[tid] = betn[tid] - g_mean[tid] * s;
            }
            __syncthreads();
            if (ty < 8) {
                int kbeg = ty * 32;
                float w[32];
#pragma unroll
                for (int i = 0; i < 32; i++)
                    w[i] = Wn[(size_t)(kbeg + i) * Nn + n0 + tx];
                float acc2 = 0.f;
#pragma unroll
                for (int i = 0; i < 32; i++) acc2 += tsv[kbeg + i] * w[i];
                red[ty][tx] = acc2;
            }
            __syncthreads();
            if (ty == 0) {
                float s = red[0][tx];
#pragma unroll
                for (int y = 1; y < 8; y++) s += red[y][tx];
                if (extran) s += extran[n0 + tx];
                uo[n0 + tx] = s;
            }
        }
    }
}

// ---------------- fused fc0+fc1: out = relu(relu(h2@fW0'+bias0') @ W3 + b3) ----------------
#define AH_OFF 0
#define AL_OFF 10240
#define BH_OFF 20480
#define BL_OFF 30720
#define BUF_SZ 40960
#define FSMEM (3 * BUF_SZ + 1024)

__global__ void __launch_bounds__(256, 1)
fused_fc(const __nv_bfloat16* __restrict__ Ah, const __nv_bfloat16* __restrict__ Al,
         const __nv_bfloat16* __restrict__ Bh, const __nv_bfloat16* __restrict__ Bl,
         const float* __restrict__ bias0,
         const __nv_bfloat16* __restrict__ W3h, const __nv_bfloat16* __restrict__ W3l,
         const float* __restrict__ bias1, float* __restrict__ Out, int M) {
    extern __shared__ char smraw[];
    uint32_t raw = s2u(smraw);
    uint32_t sbase = (raw + 1023u) & ~1023u;

    const int tid = threadIdx.x, lane = tid & 31, wid = tid >> 5;
    const int row0 = blockIdx.y * 128;
    const int wm = (wid >> 1) * 32, wn = (wid & 1) * 64;
    const int Kpad = 256, nch = 8;

    float acc[2][8][4];
#pragma unroll
    for (int i = 0; i < 2; i++)
#pragma unroll
        for (int j = 0; j < 8; j++)
#pragma unroll
            for (int c = 0; c < 4; c++) acc[i][j][c] = 0.f;

    const uint32_t a_lo = (uint32_t)((lane & 15) * ROWB + ((lane >> 4) & 1) * 16);
    const uint32_t b_lo = (uint32_t)((lane & 7) * ROWB + ((lane & 16) ? 8 * ROWB : 0) +
                                     ((lane & 8) ? 16 : 0));

    auto prefetch = [&](int ch) {
        const uint32_t bu = sbase + (ch % 3) * BUF_SZ;
        const int k0 = ch << 5;
#pragma unroll
        for (int t = 0; t < 2; t++) {
            int idx = tid + t * 256;
            int r = idx >> 2, q = idx & 3;
            size_t ao = (size_t)(row0 + r) * Kpad + k0 + q * 8;
            size_t bo = (size_t)r * Kpad + k0 + q * 8;
            uint32_t so = (uint32_t)(r * ROWB + q * 16);
            CP_ASYNC16(bu + AH_OFF + so, (const void*)(Ah + ao));
            CP_ASYNC16(bu + AL_OFF + so, (const void*)(Al + ao));
            CP_ASYNC16(bu + BH_OFF + so, (const void*)(Bh + bo));
            CP_ASYNC16(bu + BL_OFF + so, (const void*)(Bl + bo));
        }
        asm volatile("cp.async.commit_group;" ::: "memory");
    };

    prefetch(0);
    prefetch(1);

    for (int ch = 0; ch < nch; ch++) {
        if (ch + 1 < nch) { asm volatile("cp.async.wait_group 1;" ::: "memory"); }
        else              { asm volatile("cp.async.wait_group 0;" ::: "memory"); }
        __syncthreads();
        if (ch + 2 < nch) prefetch(ch + 2);

        const uint32_t bufu = sbase + (ch % 3) * BUF_SZ;
#pragma unroll
        for (int ks = 0; ks < 2; ks++) {
            uint32_t ka = bufu + AH_OFF + (uint32_t)(wm * ROWB) + a_lo + ks * 32;
            uint32_t ah0[4], ah1[4], al0[4], al1[4];
            LDX4(ah0, ka);
            LDX4(ah1, ka + 16 * ROWB);
            LDX4(al0, ka + (AL_OFF - AH_OFF));
            LDX4(al1, ka + (AL_OFF - AH_OFF) + 16 * ROWB);
#pragma unroll
            for (int nt = 0; nt < 4; nt++) {
                uint32_t kb = bufu + BH_OFF + (uint32_t)((wn + nt * 16) * ROWB) + b_lo + ks * 32;
                uint32_t bh[4], bl[4];
                LDX4(bh, kb);
                LDX4(bl, kb + (BL_OFF - BH_OFF));
                MMA(acc[0][nt * 2 + 0], ah0, bh[0], bh[1]);
                MMA(acc[1][nt * 2 + 0], ah1, bh[0], bh[1]);
                MMA(acc[0][nt * 2 + 1], ah0, bh[2], bh[3]);
                MMA(acc[1][nt * 2 + 1], ah1, bh[2], bh[3]);
                MMA(acc[0][nt * 2 + 0], al0, bh[0], bh[1]);
                MMA(acc[1][nt * 2 + 0], al1, bh[0], bh[1]);
                MMA(acc[0][nt * 2 + 1], al0, bh[2], bh[3]);
                MMA(acc[1][nt * 2 + 1], al1, bh[2], bh[3]);
                MMA(acc[0][nt * 2 + 0], ah0, bl[0], bl[1]);
                MMA(acc[1][nt * 2 + 0], ah1, bl[0], bl[1]);
                MMA(acc[0][nt * 2 + 1], ah0, bl[2], bl[3]);
                MMA(acc[1][nt * 2 + 1], ah1, bl[2], bl[3]);
            }
        }
        __syncthreads();
    }
    __syncthreads();  // stage-1 buffers now free

    const uint32_t SA = sbase;
    const uint32_t SB = sbase + 81920;

#pragma unroll
    for (int t = 0; t < 4; t++) {
        int idx = tid + t * 256;
        int c = idx >> 8, r = (idx >> 2) & 63, q = idx & 3;
        size_t go = (size_t)r * 128 + c * 32 + q * 8;
        uint32_t so = SB + c * 10240 + (uint32_t)(r * ROWB + q * 16);
        CP_ASYNC16(so, (const void*)(W3h + go));
        CP_ASYNC16(so + 5120, (const void*)(W3l + go));
    }
    asm volatile("cp.async.commit_group;" ::: "memory");

    char* sac = smraw + (sbase - raw);
#pragma unroll
    for (int mi = 0; mi < 2; mi++) {
        int rl = wm + mi * 16 + (lane >> 2);
#pragma unroll
        for (int n8 = 0; n8 < 8; n8++) {
            int cl = wn + n8 * 8 + (lane & 3) * 2;
            float bv0 = bias0[cl], bv1 = bias0[cl + 1];
            float v0 = acc[mi][n8][0] + bv0; v0 = v0 > 0.f ? v0 : 0.f;
            float v1 = acc[mi][n8][1] + bv1; v1 = v1 > 0.f ? v1 : 0.f;
            float v2 = acc[mi][n8][2] + bv0; v2 = v2 > 0.f ? v2 : 0.f;
            float v3 = acc[mi][n8][3] + bv1; v3 = v3 > 0.f ? v3 : 0.f;
            unsigned short h0, h1, h2, h3, l0, l1, l2, l3;
            bsplit(v0, h0, l0); bsplit(v1, h1, l1);
            bsplit(v2, h2, l2); bsplit(v3, h3, l3);
            uint32_t off = (uint32_t)((cl >> 5) * 20480 + rl * ROWB + (cl & 31) * 2);
            *(uint32_t*)(sac + off) = (uint32_t)h0 | ((uint32_t)h1 << 16);
            *(uint32_t*)(sac + off + 10240) = (uint32_t)l0 | ((uint32_t)l1 << 16);
            uint32_t off8 = off + 8 * ROWB;
            *(uint32_t*)(sac + off8) = (uint32_t)h2 | ((uint32_t)h3 << 16);
            *(uint32_t*)(sac + off8 + 10240) = (uint32_t)l2 | ((uint32_t)l3 << 16);
        }
    }
    asm volatile("cp.async.wait_group 0;" ::: "memory");
    __syncthreads();

    float acc2[8][4];
#pragma unroll
    for (int j = 0; j < 8; j++)
#pragma unroll
        for (int c = 0; c < 4; c++) acc2[j][c] = 0.f;

#pragma unroll
    for (int c = 0; c < 4; c++) {
#pragma unroll
        for (int ks = 0; ks < 2; ks++) {
            uint32_t ka = SA + c * 20480 + (uint32_t)(wid * 16 * ROWB) + a_lo + ks * 32;
            uint32_t ah[4], al[4];
            LDX4(ah, ka);
            LDX4(al, ka + 10240);
#pragma unroll
            for (int nt = 0; nt < 4; nt++) {
                uint32_t kb = SB + c * 10240 + (uint32_t)(nt * 16 * ROWB) + b_lo + ks * 32;
                uint32_t bh[4], bl[4];
                LDX4(bh, kb);
                LDX4(bl, kb + 5120);
                MMA(acc2[nt * 2 + 0], ah, bh[0], bh[1]);
                MMA(acc2[nt * 2 + 1], ah, bh[2], bh[3]);
                MMA(acc2[nt * 2 + 0], al, bh[0], bh[1]);
                MMA(acc2[nt * 2 + 1], al, bh[2], bh[3]);
                MMA(acc2[nt * 2 + 0], ah, bl[0], bl[1]);
                MMA(acc2[nt * 2 + 1], ah, bl[2], bl[3]);
            }
        }
    }

#pragma unroll
    for (int nt = 0; nt < 4; nt++)
#pragma unroll
        for (int h = 0; h < 2; h++) {
            int gc = nt * 16 + h * 8 + (lane & 3) * 2;
            if (gc >= 40) continue;
            float bv0 = bias1[gc], bv1 = bias1[gc + 1];
            int gr = row0 + wid * 16 + (lane >> 2);
            float* a2 = acc2[nt * 2 + h];
            if (gr < M) {
                float v0 = a2[0] + bv0; v0 = v0 > 0.f ? v0 : 0.f;
                float v1 = a2[1] + bv1; v1 = v1 > 0.f ? v1 : 0.f;
                *(float2*)&Out[(size_t)gr * 40 + gc] = make_float2(v0, v1);
            }
            if (gr + 8 < M) {
                float v2 = a2[2] + bv0; v2 = v2 > 0.f ? v2 : 0.f;
                float v3 = a2[3] + bv1; v3 = v3 > 0.f ? v3 : 0.f;
                *(float2*)&Out[(size_t)(gr + 8) * 40 + gc] = make_float2(v2, v3);
            }
        }
}

// ---------------- launch ----------------
extern "C" void kernel_launch(void* const* d_in, const int* in_sizes, int n_in,
                              void* d_out, int out_size) {
    const float* x   = (const float*)d_in[0];
    const void*  ei  = d_in[1];
    const float* W0  = (const float*)d_in[2];
    const float* b0  = (const float*)d_in[3];
    const float* g0  = (const float*)d_in[4];
    const float* be0 = (const float*)d_in[5];
    const float* W1  = (const float*)d_in[6];
    const float* b1  = (const float*)d_in[7];
    const float* g1  = (const float*)d_in[8];
    const float* be1 = (const float*)d_in[9];
    const float* fW0 = (const float*)d_in[10];
    const float* fb0 = (const float*)d_in[11];
    const float* fW1 = (const float*)d_in[12];
    const float* fb1 = (const float*)d_in[13];
    float* out = (float*)d_out;

    float *deg, *u1, *bias0p;
    __nv_bfloat16 *a1h, *a1l, *a2h, *a2l;
    __nv_bfloat16 *wth0, *wtl0, *wth1, *wtl1, *wth2, *wtl2, *wth3, *wtl3;
    cudaGetSymbolAddress((void**)&deg, g_deg);
    cudaGetSymbolAddress((void**)&u1, g_u1);
    cudaGetSymbolAddress((void**)&bias0p, g_bias0p);
    cudaGetSymbolAddress((void**)&a1h, g_a1h);
    cudaGetSymbolAddress((void**)&a1l, g_a1l);
    cudaGetSymbolAddress((void**)&a2h, g_a2h);
    cudaGetSymbolAddress((void**)&a2l, g_a2l);
    cudaGetSymbolAddress((void**)&wth0, g_wth0);
    cudaGetSymbolAddress((void**)&wtl0, g_wtl0);
    cudaGetSymbolAddress((void**)&wth1, g_wth1);
    cudaGetSymbolAddress((void**)&wtl1, g_wtl1);
    cudaGetSymbolAddress((void**)&wth2, g_wth2);
    cudaGetSymbolAddress((void**)&wtl2, g_wtl2);
    cudaGetSymbolAddress((void**)&wth3, g_wth3);
    cudaGetSymbolAddress((void**)&wtl3, g_wtl3);

    cudaFuncSetAttribute(gemm144<true>, cudaFuncAttributeMaxDynamicSharedMemorySize, GSMEM_F);
    cudaFuncSetAttribute(gemm144<false>, cudaFuncAttributeMaxDynamicSharedMemorySize, GSMEM_S);
    cudaFuncSetAttribute(fused_fc, cudaFuncAttributeMaxDynamicSharedMemorySize, FSMEM);

    const int M = N_NODES;

    // prep + degree
    prep_kernel<<<1208, 256>>>(W0, fW1, (const unsigned int*)ei);
    deg_kernel<<<(N_EDGES / 2 + 255) / 256, 256>>>(ei);

    // conv0 (fp32 A, in-kernel split): split(h1) = split(relu(deg.*(x@W0) + b0))
    gemm144<true><<<dim3(2, NBY), 384, GSMEM_F>>>(x, nullptr, nullptr, wth0, wtl0,
                                                  b0, nullptr, deg, a1h, a1l,
                                                  M, 500, 512,
                                                  W1, g0, be0, wth1, wtl1, u1, nullptr, 256, 1u);

    // conv1 (pre-split A): split(h2) = split(relu(deg.*(h1@W1' + u1) + b1))
    gemm144<false><<<dim3(2, NBY), 384, GSMEM_S>>>(nullptr, a1h, a1l, wth1, wtl1,
                                                   b1, u1, deg, a2h, a2l,
                                                   M, 256, 256,
                                                   fW0, g1, be1, wth2, wtl2, bias0p, fb0, 128, 2u);

    // fused fc0+fc1 -> out [10000][40]
    fused_fc<<<dim3(1, 79), 256, FSMEM>>>(a2h, a2l, wth2, wtl2, bias0p, wth3, wtl3, fb1, out, M);
}

// round 16
// speedup vs baseline: 1.0322x; 1.0322x over previous
#include <cuda_runtime.h>
#include <cuda_bf16.h>
#include <cstdint>

#define N_NODES 10000
#define N_EDGES 320000
#define MROWS 10176
#define NBY 70                // ceil(10000/144)
#define TOTAL_CTAS 140        // 2 * 70
#define ECH 2286              // ceil(320000/140)
#define HSIZE (1 << 20)
#define HMASK (HSIZE - 1)

// ---------------- scratch (static device globals; no allocation) ----------------
__device__ unsigned int g_htab[HSIZE];
__device__ float g_deg[N_NODES];
__device__ float g_psum[NBY * 256];
__device__ float g_psum2[NBY * 256];
__device__ float g_mean[256];
__device__ float g_rstd[256];
__device__ float g_u1[256];
__device__ float g_bias0p[128];
__device__ unsigned int g_ctr;
__device__ unsigned int g_flag;
__device__ unsigned int g_dctr;
__device__ int g_is64;
// bf16-split activations, zero-padded rows to MROWS (padding stays zero forever)
__device__ __nv_bfloat16 g_xh[MROWS * 512];
__device__ __nv_bfloat16 g_xl[MROWS * 512];
__device__ __nv_bfloat16 g_a1h[MROWS * 256];
__device__ __nv_bfloat16 g_a1l[MROWS * 256];
__device__ __nv_bfloat16 g_a2h[MROWS * 256];
__device__ __nv_bfloat16 g_a2l[MROWS * 256];
// transposed + bf16-split weights, zero-padded: [Npad][KP]
__device__ __nv_bfloat16 g_wth0[256 * 512];
__device__ __nv_bfloat16 g_wtl0[256 * 512];
__device__ __nv_bfloat16 g_wth1[256 * 256];    // BN0-scaled (folded in conv0 tail)
__device__ __nv_bfloat16 g_wtl1[256 * 256];
__device__ __nv_bfloat16 g_wth2[128 * 256];    // BN1-scaled (folded in conv1 tail)
__device__ __nv_bfloat16 g_wtl2[128 * 256];
__device__ __nv_bfloat16 g_wth3[128 * 128];
__device__ __nv_bfloat16 g_wtl3[128 * 128];

// ---------------- helpers ----------------
__device__ __forceinline__ uint32_t s2u(const void* p) {
    uint32_t a;
    asm("{ .reg .u64 t; cvta.to.shared.u64 t, %1; cvt.u32.u64 %0, t; }" : "=r"(a) : "l"(p));
    return a;
}

__device__ __forceinline__ void bsplit(float v, unsigned short& h, unsigned short& l) {
    __nv_bfloat16 hb = __float2bfloat16(v);
    float r = v - __bfloat162float(hb);
    __nv_bfloat16 lb = __float2bfloat16(r);
    h = __bfloat16_as_ushort(hb);
    l = __bfloat16_as_ushort(lb);
}

#define LDX4(r, addr) \
    asm volatile("ldmatrix.sync.aligned.m8n8.x4.shared.b16 {%0,%1,%2,%3}, [%4];" \
                 : "=r"((r)[0]), "=r"((r)[1]), "=r"((r)[2]), "=r"((r)[3]) : "r"(addr))

#define MMA(d, a, b0, b1) \
    asm volatile("mma.sync.aligned.m16n8k16.row.col.f32.bf16.bf16.f32 " \
                 "{%0,%1,%2,%3}, {%4,%5,%6,%7}, {%8,%9}, {%0,%1,%2,%3};" \
                 : "+f"((d)[0]), "+f"((d)[1]), "+f"((d)[2]), "+f"((d)[3]) \
                 : "r"((a)[0]), "r"((a)[1]), "r"((a)[2]), "r"((a)[3]), "r"(b0), "r"(b1))

#define CP_ASYNC16(dst, src) \
    asm volatile("cp.async.cg.shared.global [%0], [%1], 16;" :: "r"(dst), "l"(src))

// ---------------- prep: W0/fW1 transposes + input split + hash init + deg init + detect ---
__global__ void prep_kernel(const float* __restrict__ W0, const float* __restrict__ fW1,
                            const float* __restrict__ x, const unsigned int* __restrict__ eiw) {
    int b = blockIdx.x, tid = threadIdx.x;
    if (b < 144) {
        const float* W;
        __nv_bfloat16 *th, *tl;
        int K, KP, N, nk, lb;
        if (b < 128) { W = W0;  th = g_wth0; tl = g_wtl0; K = 500; KP = 512; N = 256; nk = 16; lb = b; }
        else         { W = fW1; th = g_wth3; tl = g_wtl3; K = 128; KP = 128; N = 40;  nk = 4;  lb = b - 128; }
        int k0 = (lb % nk) * 32, n0 = (lb / nk) * 32;
        __shared__ float t[32][33];
        int tx = tid & 31, ty = tid >> 5;
        for (int dy = ty; dy < 32; dy += 8) {
            int k = k0 + dy, n = n0 + tx;
            t[dy][tx] = (k < K && n < N) ? W[(size_t)k * N + n] : 0.f;
        }
        __syncthreads();
        for (int dy = ty; dy < 32; dy += 8) {
            int n = n0 + dy, k = k0 + tx;
            unsigned short h, l;
            bsplit(t[tx][dy], h, l);
            th[(size_t)n * KP + k] = __ushort_as_bfloat16(h);
            tl[(size_t)n * KP + k] = __ushort_as_bfloat16(l);
        }
    } else if (b < 5144) {
        int idx = (b - 144) * 256 + tid;  // over 10000*128 4-col groups
        int row = idx >> 7, c4 = (idx & 127) * 4;
        const int K = 500, KP = 512;
        float v[4] = {0.f, 0.f, 0.f, 0.f};
        if (c4 + 3 < K) {
            float4 f = *(const float4*)&x[(size_t)row * K + c4];
            v[0] = f.x; v[1] = f.y; v[2] = f.z; v[3] = f.w;
        } else {
#pragma unroll
            for (int j = 0; j < 4; j++)
                if (c4 + j < K) v[j] = x[(size_t)row * K + c4 + j];
        }
        unsigned short h[4], l[4];
#pragma unroll
        for (int j = 0; j < 4; j++) bsplit(v[j], h[j], l[j]);
        *(uint2*)&g_xh[(size_t)row * KP + c4] =
            make_uint2((uint32_t)h[0] | ((uint32_t)h[1] << 16), (uint32_t)h[2] | ((uint32_t)h[3] << 16));
        *(uint2*)&g_xl[(size_t)row * KP + c4] =
            make_uint2((uint32_t)l[0] | ((uint32_t)l[1] << 16), (uint32_t)l[2] | ((uint32_t)l[3] << 16));
    } else if (b < 6168) {
        int i = (b - 5144) * 256 + tid;
        uint4 ff = {~0u, ~0u, ~0u, ~0u};
        *(uint4*)&g_htab[i * 4] = ff;
    } else {
        int lb = b - 6168;
        int i = lb * 256 + tid;
        if (i < N_NODES) g_deg[i] = 1.0f;
        if (lb == 0 && tid < 32) {
            unsigned bad = (eiw[2 * tid + 1] != 0u) ? 1u : 0u;
            unsigned m = __ballot_sync(0xffffffffu, bad);
            if (tid == 0) {
                g_is64 = (m == 0) ? 1 : 0;
                g_flag = 0u;
                g_ctr = 0u;
                g_dctr = 0u;
            }
        }
    }
}

// ---------------- conv GEMM: BM=144, BN=128, BK=32, 384 threads (12 warps 3m x 4n) --------
// EDGE: this launch also computes deg (hash-set dedup) for its edge slice, overlapped with
// the mainloop; epilogue waits on the grid-wide deg counter before using rs.
#define ROWB 80
#define GA_H 0
#define GA_L 11520
#define GB_H 23040
#define GB_L 33280
#define GBUF 43520
#define GSMEM (3 * GBUF + 1024)

template <bool EDGE>
__global__ void __launch_bounds__(384, 1)
gemm144(const void* __restrict__ ei_raw,
        const __nv_bfloat16* __restrict__ Ah, const __nv_bfloat16* __restrict__ Al,
        const __nv_bfloat16* __restrict__ Bh, const __nv_bfloat16* __restrict__ Bl,
        const float* __restrict__ bias, const float* __restrict__ prebias,
        const float* __restrict__ rs,
        __nv_bfloat16* __restrict__ Ch, __nv_bfloat16* __restrict__ Cl,
        int M, int Kpad,
        const float* __restrict__ Wn, const float* __restrict__ gamn,
        const float* __restrict__ betn,
        __nv_bfloat16* __restrict__ tho, __nv_bfloat16* __restrict__ tlo,
        float* __restrict__ uo, const float* __restrict__ extran,
        int Nn, unsigned int gen) {
    extern __shared__ char smraw[];
    uint32_t raw = s2u(smraw);
    uint32_t sbase = (raw + 1023u) & ~1023u;
    char* sb = smraw + (sbase - raw);

    const int tid = threadIdx.x, lane = tid & 31, wid = tid >> 5;
    const int row0 = blockIdx.y * 144, col0 = blockIdx.x * 128;
    const int wm = (wid >> 2) * 48, wn = (wid & 3) * 32;
    const int nch = Kpad >> 5;
    const int Ncols = 256;
    const int unit = blockIdx.y * 2 + blockIdx.x;   // 0..139

    float acc[3][4][4];
#pragma unroll
    for (int i = 0; i < 3; i++)
#pragma unroll
        for (int j = 0; j < 4; j++)
#pragma unroll
            for (int c = 0; c < 4; c++) acc[i][j][c] = 0.f;

    const uint32_t a_lo = (uint32_t)((lane & 15) * ROWB + ((lane >> 4) & 1) * 16);
    const uint32_t b_lo = (uint32_t)((lane & 7) * ROWB + ((lane & 16) ? 8 * ROWB : 0) +
                                     ((lane & 8) ? 16 : 0));

    auto prefetch = [&](int ch) {
        const uint32_t bu = sbase + (ch % 3) * GBUF;
        const int k0 = ch << 5;
        for (int idx = tid; idx < 576; idx += 384) {
            int r = idx >> 2, q = idx & 3;
            size_t ao = (size_t)(row0 + r) * Kpad + k0 + q * 8;
            uint32_t so = (uint32_t)(r * ROWB + q * 16);
            CP_ASYNC16(bu + GA_H + so, (const void*)(Ah + ao));
            CP_ASYNC16(bu + GA_L + so, (const void*)(Al + ao));
        }
        for (int idx = tid; idx < 512; idx += 384) {
            int r = idx >> 2, q = idx & 3;
            size_t bo = (size_t)(col0 + r) * Kpad + k0 + q * 8;
            uint32_t so = (uint32_t)(r * ROWB + q * 16);
            CP_ASYNC16(bu + GB_H + so, (const void*)(Bh + bo));
            CP_ASYNC16(bu + GB_L + so, (const void*)(Bl + bo));
        }
        asm volatile("cp.async.commit_group;" ::: "memory");
    };

    prefetch(0);
    prefetch(1);

    // ---- degree slice (conv0 only): overlapped with inflight cp.async ----
    if (EDGE) {
        const int is64 = g_is64;
        int ebeg = unit * ECH;
        int eend = ebeg + ECH;
        if (eend > N_EDGES) eend = N_EDGES;
        for (int e = ebeg + tid; e < eend; e += 384) {
            int s, d;
            if (is64) {
                const long long* p = (const long long*)ei_raw;
                s = (int)p[e];
                d = (int)p[e + N_EDGES];
            } else {
                const int* p = (const int*)ei_raw;
                s = p[e];
                d = p[e + N_EDGES];
            }
            if ((unsigned)s >= N_NODES || (unsigned)d >= N_NODES) continue;
            if (s == d) continue;  // diagonal already 1 via eye()
            unsigned int k = (unsigned int)s * (unsigned int)N_NODES + (unsigned int)d;
            unsigned int h = (k * 2654435761u) >> 12;
            for (unsigned int j = 0;; j++) {
                unsigned int slot = (h + j) & HMASK;
                unsigned int old = atomicCAS(&g_htab[slot], 0xFFFFFFFFu, k);
                if (old == 0xFFFFFFFFu) { atomicAdd(&g_deg[s], 1.0f); break; }
                if (old == k) break;
            }
        }
        __threadfence();
        __syncthreads();
        if (tid == 0) atomicAdd(&g_dctr, 1u);
    }

    for (int ch = 0; ch < nch; ch++) {
        if (ch + 1 < nch) { asm volatile("cp.async.wait_group 1;" ::: "memory"); }
        else              { asm volatile("cp.async.wait_group 0;" ::: "memory"); }
        __syncthreads();
        if (ch + 2 < nch) prefetch(ch + 2);

        const uint32_t bufu = sbase + (ch % 3) * GBUF;
#pragma unroll
        for (int ks = 0; ks < 2; ks++) {
            uint32_t ah[3][4], al[3][4];
#pragma unroll
            for (int mt = 0; mt < 3; mt++) {
                uint32_t ka = bufu + GA_H + (uint32_t)((wm + mt * 16) * ROWB) + a_lo + ks * 32;
                LDX4(ah[mt], ka);
                LDX4(al[mt], ka + (GA_L - GA_H));
            }
#pragma unroll
            for (int nt = 0; nt < 2; nt++) {
                uint32_t kb = bufu + GB_H + (uint32_t)((wn + nt * 16) * ROWB) + b_lo + ks * 32;
                uint32_t bh[4], bl[4];
                LDX4(bh, kb);
                LDX4(bl, kb + (GB_L - GB_H));
#pragma unroll
                for (int mt = 0; mt < 3; mt++) {
                    MMA(acc[mt][nt * 2 + 0], ah[mt], bh[0], bh[1]);
                    MMA(acc[mt][nt * 2 + 1], ah[mt], bh[2], bh[3]);
                    MMA(acc[mt][nt * 2 + 0], al[mt], bh[0], bh[1]);
                    MMA(acc[mt][nt * 2 + 1], al[mt], bh[2], bh[3]);
                    MMA(acc[mt][nt * 2 + 0], ah[mt], bl[0], bl[1]);
                    MMA(acc[mt][nt * 2 + 1], ah[mt], bl[2], bl[3]);
                }
            }
        }
        __syncthreads();
    }

    // ---- wait for grid-wide degree completion before reading rs (conv0 only) ----
    if (EDGE) {
        if (tid == 0) {
            while (atomicAdd(&g_dctr, 0u) < TOTAL_CTAS) __nanosleep(64);
        }
        __syncthreads();
        __threadfence();
    }

    // epilogue: v = relu(rs*(acc + u) + bias); bf16-split stores + fused column stats
    float ts[4][2], ts2[4][2];
#pragma unroll
    for (int j = 0; j < 4; j++) { ts[j][0] = ts[j][1] = ts2[j][0] = ts2[j][1] = 0.f; }
#pragma unroll
    for (int mi = 0; mi < 3; mi++) {
        int r0_ = row0 + wm + mi * 16 + (lane >> 2);
        bool ok0 = r0_ < M, ok1 = (r0_ + 8) < M;
        float d0 = 1.f, d1 = 1.f;
        if (rs) {
            if (ok0) d0 = rs[r0_];
            if (ok1) d1 = rs[r0_ + 8];
        }
#pragma unroll
        for (int j = 0; j < 4; j++) {
            int gc = col0 + wn + (j >> 1) * 16 + (j & 1) * 8 + (lane & 3) * 2;
            float bv0 = bias[gc], bv1 = bias[gc + 1];
            float u0 = prebias ? prebias[gc] : 0.f;
            float u1 = prebias ? prebias[gc + 1] : 0.f;
            float v0 = d0 * (acc[mi][j][0] + u0) + bv0; v0 = v0 > 0.f ? v0 : 0.f;
            float v1 = d0 * (acc[mi][j][1] + u1) + bv1; v1 = v1 > 0.f ? v1 : 0.f;
            float v2 = d1 * (acc[mi][j][2] + u0) + bv0; v2 = v2 > 0.f ? v2 : 0.f;
            float v3 = d1 * (acc[mi][j][3] + u1) + bv1; v3 = v3 > 0.f ? v3 : 0.f;
            if (ok0) { ts[j][0] += v0; ts2[j][0] += v0 * v0;
                       ts[j][1] += v1; ts2[j][1] += v1 * v1; }
            if (ok1) { ts[j][0] += v2; ts2[j][0] += v2 * v2;
                       ts[j][1] += v3; ts2[j][1] += v3 * v3; }
            unsigned short h0, h1_, h2_, h3_, l0, l1_, l2_, l3_;
            bsplit(v0, h0, l0); bsplit(v1, h1_, l1_);
            bsplit(v2, h2_, l2_); bsplit(v3, h3_, l3_);
            if (ok0) {
                *(uint32_t*)&Ch[(size_t)r0_ * Ncols + gc] = (uint32_t)h0 | ((uint32_t)h1_ << 16);
                *(uint32_t*)&Cl[(size_t)r0_ * Ncols + gc] = (uint32_t)l0 | ((uint32_t)l1_ << 16);
            }
            if (ok1) {
                *(uint32_t*)&Ch[(size_t)(r0_ + 8) * Ncols + gc] = (uint32_t)h2_ | ((uint32_t)h3_ << 16);
                *(uint32_t*)&Cl[(size_t)(r0_ + 8) * Ncols + gc] = (uint32_t)l2_ | ((uint32_t)l3_ << 16);
            }
        }
    }

    // warp-level stat reduce
#pragma unroll
    for (int j = 0; j < 4; j++)
#pragma unroll
        for (int k = 0; k < 2; k++) {
#pragma unroll
            for (int off = 4; off < 32; off <<= 1) {
                ts[j][k] += __shfl_xor_sync(0xffffffffu, ts[j][k], off);
                ts2[j][k] += __shfl_xor_sync(0xffffffffu, ts2[j][k], off);
            }
        }
    float* sS = (float*)sb;                 // [12][32]
    float* sS2 = sS + 12 * 32;
    __syncthreads();
    if (lane < 4) {
#pragma unroll
        for (int j = 0; j < 4; j++) {
            int cloc = (j >> 1) * 16 + (j & 1) * 8 + lane * 2;
            sS[wid * 32 + cloc] = ts[j][0];
            sS[wid * 32 + cloc + 1] = ts[j][1];
            sS2[wid * 32 + cloc] = ts2[j][0];
            sS2[wid * 32 + cloc + 1] = ts2[j][1];
        }
    }
    __syncthreads();
    if (tid < 128) {
        int c = tid;
        int g = c >> 5, cloc = c & 31;
        float s = 0.f, s2 = 0.f;
#pragma unroll
        for (int w = 0; w < 3; w++) {
            s += sS[(g + 4 * w) * 32 + cloc];
            s2 += sS2[(g + 4 * w) * 32 + cloc];
        }
        g_psum[blockIdx.y * 256 + col0 + c] = s;
        g_psum2[blockIdx.y * 256 + col0 + c] = s2;
        __threadfence();
    }
    __syncthreads();

    // ---- grid-resident handoff: last CTA finalizes stats + releases flag ----
    __shared__ int s_last;
    if (tid == 0) {
        unsigned int o = atomicAdd(&g_ctr, 1u);
        s_last = (o == TOTAL_CTAS - 1) ? 1 : 0;
    }
    __syncthreads();
    if (s_last) {
        __threadfence();
        if (tid < 256) {
            int c = tid;
            float s = 0.f, s2 = 0.f;
            for (int b = 0; b < NBY; b++) { s += g_psum[b * 256 + c]; s2 += g_psum2[b * 256 + c]; }
            float m = s / (float)M;
            float var = s2 / (float)M - m * m;
            g_mean[c] = m;
            g_rstd[c] = rsqrtf(var + 1e-5f);
        }
        if (tid == 0) g_ctr = 0;
        __threadfence();
        __syncthreads();
        if (tid == 0) atomicExch(&g_flag, gen);
    } else {
        if (tid == 0) {
            while (atomicAdd(&g_flag, 0u) < gen) __nanosleep(64);
        }
        __syncthreads();
        __threadfence();
    }

    // ---- cooperative BN fold ----
    {
        const int Kn = 256, ntk = 8;
        int ntiles = ntk * (Nn >> 5);
        int ngemv = Nn >> 5;
        if (unit < ntiles) {
            __shared__ float t[32][33];
            __shared__ float ss[32];
            int k0 = (unit % ntk) * 32, n0 = (unit / ntk) * 32;
            int tx = tid & 31, ty = tid >> 5;
            if (tid < 32) ss[tid] = g_rstd[k0 + tid] * gamn[k0 + tid];
            for (int dy = ty; dy < 32; dy += 12)
                t[dy][tx] = Wn[(size_t)(k0 + dy) * Nn + n0 + tx];
            __syncthreads();
            for (int dy = ty; dy < 32; dy += 12) {
                int n = n0 + dy, k = k0 + tx;
                unsigned short h, l;
                bsplit(t[tx][dy] * ss[tx], h, l);
                tho[(size_t)n * Kn + k] = __ushort_as_bfloat16(h);
                tlo[(size_t)n * Kn + k] = __ushort_as_bfloat16(l);
            }
        } else if (unit < ntiles + ngemv) {
            int n0 = (unit - ntiles) * 32;
            int tx = tid & 31, ty = tid >> 5;
            __shared__ float tsv[256];
            __shared__ float red[8][33];
            if (tid < 256) {
                float s = g_rstd[tid] * gamn[tid];
                tsv[tid] = betn[tid] - g_mean[tid] * s;
            }
            __syncthreads();
            if (ty < 8) {
                int kbeg = ty * 32;
                float w[32];
#pragma unroll
                for (int i = 0; i < 32; i++)
                    w[i] = Wn[(size_t)(kbeg + i) * Nn + n0 + tx];
                float acc2 = 0.f;
#pragma unroll
                for (int i = 0; i < 32; i++) acc2 += tsv[kbeg + i] * w[i];
                red[ty][tx] = acc2;
            }
            __syncthreads();
            if (ty == 0) {
                float s = red[0][tx];
#pragma unroll
                for (int y = 1; y < 8; y++) s += red[y][tx];
                if (extran) s += extran[n0 + tx];
                uo[n0 + tx] = s;
            }
        }
    }
}

// ---------------- fused fc0+fc1: out = relu(relu(h2@fW0'+bias0') @ W3 + b3) ----------------
#define AH_OFF 0
#define AL_OFF 10240
#define BH_OFF 20480
#define BL_OFF 30720
#define BUF_SZ 40960
#define FSMEM (3 * BUF_SZ + 1024)

__global__ void __launch_bounds__(256, 1)
fused_fc(const __nv_bfloat16* __restrict__ Ah, const __nv_bfloat16* __restrict__ Al,
         const __nv_bfloat16* __restrict__ Bh, const __nv_bfloat16* __restrict__ Bl,
         const float* __restrict__ bias0,
         const __nv_bfloat16* __restrict__ W3h, const __nv_bfloat16* __restrict__ W3l,
         const float* __restrict__ bias1, float* __restrict__ Out, int M) {
    extern __shared__ char smraw[];
    uint32_t raw = s2u(smraw);
    uint32_t sbase = (raw + 1023u) & ~1023u;

    const int tid = threadIdx.x, lane = tid & 31, wid = tid >> 5;
    const int row0 = blockIdx.y * 128;
    const int wm = (wid >> 1) * 32, wn = (wid & 1) * 64;
    const int Kpad = 256, nch = 8;

    float acc[2][8][4];
#pragma unroll
    for (int i = 0; i < 2; i++)
#pragma unroll
        for (int j = 0; j < 8; j++)
#pragma unroll
            for (int c = 0; c < 4; c++) acc[i][j][c] = 0.f;

    const uint32_t a_lo = (uint32_t)((lane & 15) * ROWB + ((lane >> 4) & 1) * 16);
    const uint32_t b_lo = (uint32_t)((lane & 7) * ROWB + ((lane & 16) ? 8 * ROWB : 0) +
                                     ((lane & 8) ? 16 : 0));

    auto prefetch = [&](int ch) {
        const uint32_t bu = sbase + (ch % 3) * BUF_SZ;
        const int k0 = ch << 5;
#pragma unroll
        for (int t = 0; t < 2; t++) {
            int idx = tid + t * 256;
            int r = idx >> 2, q = idx & 3;
            size_t ao = (size_t)(row0 + r) * Kpad + k0 + q * 8;
            size_t bo = (size_t)r * Kpad + k0 + q * 8;
            uint32_t so = (uint32_t)(r * ROWB + q * 16);
            CP_ASYNC16(bu + AH_OFF + so, (const void*)(Ah + ao));
            CP_ASYNC16(bu + AL_OFF + so, (const void*)(Al + ao));
            CP_ASYNC16(bu + BH_OFF + so, (const void*)(Bh + bo));
            CP_ASYNC16(bu + BL_OFF + so, (const void*)(Bl + bo));
        }
        asm volatile("cp.async.commit_group;" ::: "memory");
    };

    prefetch(0);
    prefetch(1);

    for (int ch = 0; ch < nch; ch++) {
        if (ch + 1 < nch) { asm volatile("cp.async.wait_group 1;" ::: "memory"); }
        else              { asm volatile("cp.async.wait_group 0;" ::: "memory"); }
        __syncthreads();
        if (ch + 2 < nch) prefetch(ch + 2);

        const uint32_t bufu = sbase + (ch % 3) * BUF_SZ;
#pragma unroll
        for (int ks = 0; ks < 2; ks++) {
            uint32_t ka = bufu + AH_OFF + (uint32_t)(wm * ROWB) + a_lo + ks * 32;
            uint32_t ah0[4], ah1[4], al0[4], al1[4];
            LDX4(ah0, ka);
            LDX4(ah1, ka + 16 * ROWB);
            LDX4(al0, ka + (AL_OFF - AH_OFF));
            LDX4(al1, ka + (AL_OFF - AH_OFF) + 16 * ROWB);
#pragma unroll
            for (int nt = 0; nt < 4; nt++) {
                uint32_t kb = bufu + BH_OFF + (uint32_t)((wn + nt * 16) * ROWB) + b_lo + ks * 32;
                uint32_t bh[4], bl[4];
                LDX4(bh, kb);
                LDX4(bl, kb + (BL_OFF - BH_OFF));
                MMA(acc[0][nt * 2 + 0], ah0, bh[0], bh[1]);
                MMA(acc[1][nt * 2 + 0], ah1, bh[0], bh[1]);
                MMA(acc[0][nt * 2 + 1], ah0, bh[2], bh[3]);
                MMA(acc[1][nt * 2 + 1], ah1, bh[2], bh[3]);
                MMA(acc[0][nt * 2 + 0], al0, bh[0], bh[1]);
                MMA(acc[1][nt * 2 + 0], al1, bh[0], bh[1]);
                MMA(acc[0][nt * 2 + 1], al0, bh[2], bh[3]);
                MMA(acc[1][nt * 2 + 1], al1, bh[2], bh[3]);
                MMA(acc[0][nt * 2 + 0], ah0, bl[0], bl[1]);
                MMA(acc[1][nt * 2 + 0], ah1, bl[0], bl[1]);
                MMA(acc[0][nt * 2 + 1], ah0, bl[2], bl[3]);
                MMA(acc[1][nt * 2 + 1], ah1, bl[2], bl[3]);
            }
        }
        __syncthreads();
    }
    __syncthreads();  // stage-1 buffers now free

    const uint32_t SA = sbase;
    const uint32_t SB = sbase + 81920;

#pragma unroll
    for (int t = 0; t < 4; t++) {
        int idx = tid + t * 256;
        int c = idx >> 8, r = (idx >> 2) & 63, q = idx & 3;
        size_t go = (size_t)r * 128 + c * 32 + q * 8;
        uint32_t so = SB + c * 10240 + (uint32_t)(r * ROWB + q * 16);
        CP_ASYNC16(so, (const void*)(W3h + go));
        CP_ASYNC16(so + 5120, (const void*)(W3l + go));
    }
    asm volatile("cp.async.commit_group;" ::: "memory");

    char* sac = smraw + (sbase - raw);
#pragma unroll
    for (int mi = 0; mi < 2; mi++) {
        int rl = wm + mi * 16 + (lane >> 2);
#pragma unroll
        for (int n8 = 0; n8 < 8; n8++) {
            int cl = wn + n8 * 8 + (lane & 3) * 2;
            float bv0 = bias0[cl], bv1 = bias0[cl + 1];
            float v0 = acc[mi][n8][0] + bv0; v0 = v0 > 0.f ? v0 : 0.f;
            float v1 = acc[mi][n8][1] + bv1; v1 = v1 > 0.f ? v1 : 0.f;
            float v2 = acc[mi][n8][2] + bv0; v2 = v2 > 0.f ? v2 : 0.f;
            float v3 = acc[mi][n8][3] + bv1; v3 = v3 > 0.f ? v3 : 0.f;
            unsigned short h0, h1, h2, h3, l0, l1, l2, l3;
            bsplit(v0, h0, l0); bsplit(v1, h1, l1);
            bsplit(v2, h2, l2); bsplit(v3, h3, l3);
            uint32_t off = (uint32_t)((cl >> 5) * 20480 + rl * ROWB + (cl & 31) * 2);
            *(uint32_t*)(sac + off) = (uint32_t)h0 | ((uint32_t)h1 << 16);
            *(uint32_t*)(sac + off + 10240) = (uint32_t)l0 | ((uint32_t)l1 << 16);
            uint32_t off8 = off + 8 * ROWB;
            *(uint32_t*)(sac + off8) = (uint32_t)h2 | ((uint32_t)h3 << 16);
            *(uint32_t*)(sac + off8 + 10240) = (uint32_t)l2 | ((uint32_t)l3 << 16);
        }
    }
    asm volatile("cp.async.wait_group 0;" ::: "memory");
    __syncthreads();

    float acc2[8][4];
#pragma unroll
    for (int j = 0; j < 8; j++)
#pragma unroll
        for (int c = 0; c < 4; c++) acc2[j][c] = 0.f;

#pragma unroll
    for (int c = 0; c < 4; c++) {
#pragma unroll
        for (int ks = 0; ks < 2; ks++) {
            uint32_t ka = SA + c * 20480 + (uint32_t)(wid * 16 * ROWB) + a_lo + ks * 32;
            uint32_t ah[4], al[4];
            LDX4(ah, ka);
            LDX4(al, ka + 10240);
#pragma unroll
            for (int nt = 0; nt < 4; nt++) {
                uint32_t kb = SB + c * 10240 + (uint32_t)(nt * 16 * ROWB) + b_lo + ks * 32;
                uint32_t bh[4], bl[4];
                LDX4(bh, kb);
                LDX4(bl, kb + 5120);
                MMA(acc2[nt * 2 + 0], ah, bh[0], bh[1]);
                MMA(acc2[nt * 2 + 1], ah, bh[2], bh[3]);
                MMA(acc2[nt * 2 + 0], al, bh[0], bh[1]);
                MMA(acc2[nt * 2 + 1], al, bh[2], bh[3]);
                MMA(acc2[nt * 2 + 0], ah, bl[0], bl[1]);
                MMA(acc2[nt * 2 + 1], ah, bl[2], bl[3]);
            }
        }
    }

#pragma unroll
    for (int nt = 0; nt < 4; nt++)
#pragma unroll
        for (int h = 0; h < 2; h++) {
            int gc = nt * 16 + h * 8 + (lane & 3) * 2;
            if (gc >= 40) continue;
            float bv0 = bias1[gc], bv1 = bias1[gc + 1];
            int gr = row0 + wid * 16 + (lane >> 2);
            float* a2 = acc2[nt * 2 + h];
            if (gr < M) {
                float v0 = a2[0] + bv0; v0 = v0 > 0.f ? v0 : 0.f;
                float v1 = a2[1] + bv1; v1 = v1 > 0.f ? v1 : 0.f;
                *(float2*)&Out[(size_t)gr * 40 + gc] = make_float2(v0, v1);
            }
            if (gr + 8 < M) {
                float v2 = a2[2] + bv0; v2 = v2 > 0.f ? v2 : 0.f;
                float v3 = a2[3] + bv1; v3 = v3 > 0.f ? v3 : 0.f;
                *(float2*)&Out[(size_t)(gr + 8) * 40 + gc] = make_float2(v2, v3);
            }
        }
}

// ---------------- launch ----------------
extern "C" void kernel_launch(void* const* d_in, const int* in_sizes, int n_in,
                              void* d_out, int out_size) {
    const float* x   = (const float*)d_in[0];
    const void*  ei  = d_in[1];
    const float* W0  = (const float*)d_in[2];
    const float* b0  = (const float*)d_in[3];
    const float* g0  = (const float*)d_in[4];
    const float* be0 = (const float*)d_in[5];
    const float* W1  = (const float*)d_in[6];
    const float* b1  = (const float*)d_in[7];
    const float* g1  = (const float*)d_in[8];
    const float* be1 = (const float*)d_in[9];
    const float* fW0 = (const float*)d_in[10];
    const float* fb0 = (const float*)d_in[11];
    const float* fW1 = (const float*)d_in[12];
    const float* fb1 = (const float*)d_in[13];
    float* out = (float*)d_out;

    float *deg, *u1, *bias0p;
    __nv_bfloat16 *xh, *xl, *a1h, *a1l, *a2h, *a2l;
    __nv_bfloat16 *wth0, *wtl0, *wth1, *wtl1, *wth2, *wtl2, *wth3, *wtl3;
    cudaGetSymbolAddress((void**)&deg, g_deg);
    cudaGetSymbolAddress((void**)&u1, g_u1);
    cudaGetSymbolAddress((void**)&bias0p, g_bias0p);
    cudaGetSymbolAddress((void**)&xh, g_xh);
    cudaGetSymbolAddress((void**)&xl, g_xl);
    cudaGetSymbolAddress((void**)&a1h, g_a1h);
    cudaGetSymbolAddress((void**)&a1l, g_a1l);
    cudaGetSymbolAddress((void**)&a2h, g_a2h);
    cudaGetSymbolAddress((void**)&a2l, g_a2l);
    cudaGetSymbolAddress((void**)&wth0, g_wth0);
    cudaGetSymbolAddress((void**)&wtl0, g_wtl0);
    cudaGetSymbolAddress((void**)&wth1, g_wth1);
    cudaGetSymbolAddress((void**)&wtl1, g_wtl1);
    cudaGetSymbolAddress((void**)&wth2, g_wth2);
    cudaGetSymbolAddress((void**)&wtl2, g_wtl2);
    cudaGetSymbolAddress((void**)&wth3, g_wth3);
    cudaGetSymbolAddress((void**)&wtl3, g_wtl3);

    cudaFuncSetAttribute(gemm144<true>, cudaFuncAttributeMaxDynamicSharedMemorySize, GSMEM);
    cudaFuncSetAttribute(gemm144<false>, cudaFuncAttributeMaxDynamicSharedMemorySize, GSMEM);
    cudaFuncSetAttribute(fused_fc, cudaFuncAttributeMaxDynamicSharedMemorySize, FSMEM);

    const int M = N_NODES;

    // prep (transposes + x split + hash init + deg init + detect + flag resets)
    prep_kernel<<<6208, 256>>>(W0, fW1, x, (const unsigned int*)ei);

    // conv0 (+ inlined degree scatter): split(h1) = split(relu(deg.*(x@W0) + b0))
    gemm144<true><<<dim3(2, NBY), 384, GSMEM>>>(ei, xh, xl, wth0, wtl0, b0, nullptr, deg,
                                                a1h, a1l, M, 512,
                                                W1, g0, be0, wth1, wtl1, u1, nullptr, 256, 1u);

    // conv1: split(h2) = split(relu(deg.*(h1@W1' + u1) + b1))
    gemm144<false><<<dim3(2, NBY), 384, GSMEM>>>(nullptr, a1h, a1l, wth1, wtl1, b1, u1, deg,
                                                 a2h, a2l, M, 256,
                                                 fW0, g1, be1, wth2, wtl2, bias0p, fb0, 128, 2u);

    // fused fc0+fc1 -> out [10000][40]
    fused_fc<<<dim3(1, 79), 256, FSMEM>>>(a2h, a2l, wth2, wtl2, bias0p, wth3, wtl3, fb1, out, M);
}

// round 17
// speedup vs baseline: 1.1034x; 1.0689x over previous
#include <cuda_runtime.h>
#include <cuda_bf16.h>
#include <cstdint>

#define N_NODES 10000
#define N_EDGES 320000
#define MROWS 10176
#define NBY 70                // ceil(10000/144)
#define TOTAL_CTAS 140        // 2 * 70
#define HSIZE (1 << 20)
#define HMASK (HSIZE - 1)

// ---------------- scratch (static device globals; no allocation) ----------------
__device__ unsigned int g_htab[HSIZE];
__device__ float g_deg[N_NODES];
__device__ float g_psum[NBY * 256];
__device__ float g_psum2[NBY * 256];
__device__ float g_mean[256];
__device__ float g_rstd[256];
__device__ float g_u1[256];
__device__ float g_bias0p[128];
__device__ unsigned int g_ctr;
__device__ unsigned int g_flag;
__device__ int g_is64;
// bf16-split activations, zero-padded rows to MROWS (padding stays zero forever)
__device__ __nv_bfloat16 g_xh[MROWS * 512];
__device__ __nv_bfloat16 g_xl[MROWS * 512];
__device__ __nv_bfloat16 g_a1h[MROWS * 256];
__device__ __nv_bfloat16 g_a1l[MROWS * 256];
__device__ __nv_bfloat16 g_a2h[MROWS * 256];
__device__ __nv_bfloat16 g_a2l[MROWS * 256];
// transposed + bf16-split weights, zero-padded: [Npad][KP]
__device__ __nv_bfloat16 g_wth0[256 * 512];
__device__ __nv_bfloat16 g_wtl0[256 * 512];
__device__ __nv_bfloat16 g_wth1[256 * 256];    // BN0-scaled (folded in conv0 tail)
__device__ __nv_bfloat16 g_wtl1[256 * 256];
__device__ __nv_bfloat16 g_wth2[128 * 256];    // BN1-scaled (folded in conv1 tail)
__device__ __nv_bfloat16 g_wtl2[128 * 256];
__device__ __nv_bfloat16 g_wth3[128 * 128];
__device__ __nv_bfloat16 g_wtl3[128 * 128];

// ---------------- helpers ----------------
__device__ __forceinline__ uint32_t s2u(const void* p) {
    uint32_t a;
    asm("{ .reg .u64 t; cvta.to.shared.u64 t, %1; cvt.u32.u64 %0, t; }" : "=r"(a) : "l"(p));
    return a;
}

__device__ __forceinline__ void bsplit(float v, unsigned short& h, unsigned short& l) {
    __nv_bfloat16 hb = __float2bfloat16(v);
    float r = v - __bfloat162float(hb);
    __nv_bfloat16 lb = __float2bfloat16(r);
    h = __bfloat16_as_ushort(hb);
    l = __bfloat16_as_ushort(lb);
}

#define LDX4(r, addr) \
    asm volatile("ldmatrix.sync.aligned.m8n8.x4.shared.b16 {%0,%1,%2,%3}, [%4];" \
                 : "=r"((r)[0]), "=r"((r)[1]), "=r"((r)[2]), "=r"((r)[3]) : "r"(addr))

#define MMA(d, a, b0, b1) \
    asm volatile("mma.sync.aligned.m16n8k16.row.col.f32.bf16.bf16.f32 " \
                 "{%0,%1,%2,%3}, {%4,%5,%6,%7}, {%8,%9}, {%0,%1,%2,%3};" \
                 : "+f"((d)[0]), "+f"((d)[1]), "+f"((d)[2]), "+f"((d)[3]) \
                 : "r"((a)[0]), "r"((a)[1]), "r"((a)[2]), "r"((a)[3]), "r"(b0), "r"(b1))

#define CP_ASYNC16(dst, src) \
    asm volatile("cp.async.cg.shared.global [%0], [%1], 16;" :: "r"(dst), "l"(src))

// ---------------- prep: W0/fW1 transposes + input split + hash init + deg init + detect ---
__global__ void prep_kernel(const float* __restrict__ W0, const float* __restrict__ fW1,
                            const float* __restrict__ x, const unsigned int* __restrict__ eiw) {
    int b = blockIdx.x, tid = threadIdx.x;
    if (b < 144) {
        const float* W;
        __nv_bfloat16 *th, *tl;
        int K, KP, N, nk, lb;
        if (b < 128) { W = W0;  th = g_wth0; tl = g_wtl0; K = 500; KP = 512; N = 256; nk = 16; lb = b; }
        else         { W = fW1; th = g_wth3; tl = g_wtl3; K = 128; KP = 128; N = 40;  nk = 4;  lb = b - 128; }
        int k0 = (lb % nk) * 32, n0 = (lb / nk) * 32;
        __shared__ float t[32][33];
        int tx = tid & 31, ty = tid >> 5;
        for (int dy = ty; dy < 32; dy += 8) {
            int k = k0 + dy, n = n0 + tx;
            t[dy][tx] = (k < K && n < N) ? W[(size_t)k * N + n] : 0.f;
        }
        __syncthreads();
        for (int dy = ty; dy < 32; dy += 8) {
            int n = n0 + dy, k = k0 + tx;
            unsigned short h, l;
            bsplit(t[tx][dy], h, l);
            th[(size_t)n * KP + k] = __ushort_as_bfloat16(h);
            tl[(size_t)n * KP + k] = __ushort_as_bfloat16(l);
        }
    } else if (b < 5144) {
        int idx = (b - 144) * 256 + tid;  // over 10000*128 4-col groups
        int row = idx >> 7, c4 = (idx & 127) * 4;
        const int K = 500, KP = 512;
        float v[4] = {0.f, 0.f, 0.f, 0.f};
        if (c4 + 3 < K) {
            float4 f = *(const float4*)&x[(size_t)row * K + c4];
            v[0] = f.x; v[1] = f.y; v[2] = f.z; v[3] = f.w;
        } else {
#pragma unroll
            for (int j = 0; j < 4; j++)
                if (c4 + j < K) v[j] = x[(size_t)row * K + c4 + j];
        }
        unsigned short h[4], l[4];
#pragma unroll
        for (int j = 0; j < 4; j++) bsplit(v[j], h[j], l[j]);
        *(uint2*)&g_xh[(size_t)row * KP + c4] =
            make_uint2((uint32_t)h[0] | ((uint32_t)h[1] << 16), (uint32_t)h[2] | ((uint32_t)h[3] << 16));
        *(uint2*)&g_xl[(size_t)row * KP + c4] =
            make_uint2((uint32_t)l[0] | ((uint32_t)l[1] << 16), (uint32_t)l[2] | ((uint32_t)l[3] << 16));
    } else if (b < 6168) {
        int i = (b - 5144) * 256 + tid;
        uint4 ff = {~0u, ~0u, ~0u, ~0u};
        *(uint4*)&g_htab[i * 4] = ff;
    } else {
        int lb = b - 6168;
        int i = lb * 256 + tid;
        if (i < N_NODES) g_deg[i] = 1.0f;
        if (lb == 0 && tid < 32) {
            unsigned bad = (eiw[2 * tid + 1] != 0u) ? 1u : 0u;
            unsigned m = __ballot_sync(0xffffffffu, bad);
            if (tid == 0) {
                g_is64 = (m == 0) ? 1 : 0;
                g_flag = 0u;
                g_ctr = 0u;
            }
        }
    }
}

// ---------------- degree with hash-set dedup, 2 edges/thread ----------------
__global__ void deg_kernel(const void* __restrict__ ei_raw) {
    int t = blockIdx.x * blockDim.x + threadIdx.x;
    const int half = N_EDGES / 2;
    if (t >= half) return;
    const int is64 = g_is64;
#pragma unroll
    for (int u = 0; u < 2; u++) {
        int e = t + u * half;
        int s, d;
        if (is64) {
            const long long* p = (const long long*)ei_raw;
            s = (int)p[e];
            d = (int)p[e + N_EDGES];
        } else {
            const int* p = (const int*)ei_raw;
            s = p[e];
            d = p[e + N_EDGES];
        }
        if ((unsigned)s >= N_NODES || (unsigned)d >= N_NODES) continue;
        if (s == d) continue;
        unsigned int k = (unsigned int)s * (unsigned int)N_NODES + (unsigned int)d;
        unsigned int h = (k * 2654435761u) >> 12;
        for (unsigned int j = 0;; j++) {
            unsigned int slot = (h + j) & HMASK;
            unsigned int old = atomicCAS(&g_htab[slot], 0xFFFFFFFFu, k);
            if (old == 0xFFFFFFFFu) { atomicAdd(&g_deg[s], 1.0f); break; }
            if (old == k) break;
        }
    }
}

// ---------------- conv GEMM: BM=144, BN=128, BK=32, 384 threads (12 warps 3m x 4n) --------
#define ROWB 80
#define GA_H 0
#define GA_L 11520
#define GB_H 23040
#define GB_L 33280
#define GBUF 43520
#define GSMEM (3 * GBUF + 1024)

__global__ void __launch_bounds__(384, 1)
gemm144(const __nv_bfloat16* __restrict__ Ah, const __nv_bfloat16* __restrict__ Al,
        const __nv_bfloat16* __restrict__ Bh, const __nv_bfloat16* __restrict__ Bl,
        const float* __restrict__ bias, const float* __restrict__ prebias,
        const float* __restrict__ rs,
        __nv_bfloat16* __restrict__ Ch, __nv_bfloat16* __restrict__ Cl,
        int M, int Kpad,
        const float* __restrict__ Wn, const float* __restrict__ gamn,
        const float* __restrict__ betn,
        __nv_bfloat16* __restrict__ tho, __nv_bfloat16* __restrict__ tlo,
        float* __restrict__ uo, const float* __restrict__ extran,
        int Nn, unsigned int gen) {
    extern __shared__ char smraw[];
    uint32_t raw = s2u(smraw);
    uint32_t sbase = (raw + 1023u) & ~1023u;
    char* sb = smraw + (sbase - raw);

    const int tid = threadIdx.x, lane = tid & 31, wid = tid >> 5;
    const int row0 = blockIdx.y * 144, col0 = blockIdx.x * 128;
    const int wm = (wid >> 2) * 48, wn = (wid & 3) * 32;
    const int nch = Kpad >> 5;
    const int Ncols = 256;

    float acc[3][4][4];
#pragma unroll
    for (int i = 0; i < 3; i++)
#pragma unroll
        for (int j = 0; j < 4; j++)
#pragma unroll
            for (int c = 0; c < 4; c++) acc[i][j][c] = 0.f;

    const uint32_t a_lo = (uint32_t)((lane & 15) * ROWB + ((lane >> 4) & 1) * 16);
    const uint32_t b_lo = (uint32_t)((lane & 7) * ROWB + ((lane & 16) ? 8 * ROWB : 0) +
                                     ((lane & 8) ? 16 : 0));

    auto prefetch = [&](int ch) {
        const uint32_t bu = sbase + (ch % 3) * GBUF;
        const int k0 = ch << 5;
        for (int idx = tid; idx < 576; idx += 384) {
            int r = idx >> 2, q = idx & 3;
            size_t ao = (size_t)(row0 + r) * Kpad + k0 + q * 8;
            uint32_t so = (uint32_t)(r * ROWB + q * 16);
            CP_ASYNC16(bu + GA_H + so, (const void*)(Ah + ao));
            CP_ASYNC16(bu + GA_L + so, (const void*)(Al + ao));
        }
        for (int idx = tid; idx < 512; idx += 384) {
            int r = idx >> 2, q = idx & 3;
            size_t bo = (size_t)(col0 + r) * Kpad + k0 + q * 8;
            uint32_t so = (uint32_t)(r * ROWB + q * 16);
            CP_ASYNC16(bu + GB_H + so, (const void*)(Bh + bo));
            CP_ASYNC16(bu + GB_L + so, (const void*)(Bl + bo));
        }
        asm volatile("cp.async.commit_group;" ::: "memory");
    };

    prefetch(0);
    prefetch(1);

    for (int ch = 0; ch < nch; ch++) {
        if (ch + 1 < nch) { asm volatile("cp.async.wait_group 1;" ::: "memory"); }
        else              { asm volatile("cp.async.wait_group 0;" ::: "memory"); }
        __syncthreads();
        if (ch + 2 < nch) prefetch(ch + 2);

        const uint32_t bufu = sbase + (ch % 3) * GBUF;
#pragma unroll
        for (int ks = 0; ks < 2; ks++) {
            uint32_t ah[3][4], al[3][4];
#pragma unroll
            for (int mt = 0; mt < 3; mt++) {
                uint32_t ka = bufu + GA_H + (uint32_t)((wm + mt * 16) * ROWB) + a_lo + ks * 32;
                LDX4(ah[mt], ka);
                LDX4(al[mt], ka + (GA_L - GA_H));
            }
#pragma unroll
            for (int nt = 0; nt < 2; nt++) {
                uint32_t kb = bufu + GB_H + (uint32_t)((wn + nt * 16) * ROWB) + b_lo + ks * 32;
                uint32_t bh[4], bl[4];
                LDX4(bh, kb);
                LDX4(bl, kb + (GB_L - GB_H));
#pragma unroll
                for (int mt = 0; mt < 3; mt++) {
                    MMA(acc[mt][nt * 2 + 0], ah[mt], bh[0], bh[1]);
                    MMA(acc[mt][nt * 2 + 1], ah[mt], bh[2], bh[3]);
                    MMA(acc[mt][nt * 2 + 0], al[mt], bh[0], bh[1]);
                    MMA(acc[mt][nt * 2 + 1], al[mt], bh[2], bh[3]);
                    MMA(acc[mt][nt * 2 + 0], ah[mt], bl[0], bl[1]);
                    MMA(acc[mt][nt * 2 + 1], ah[mt], bl[2], bl[3]);
                }
            }
        }
        __syncthreads();
    }

    // epilogue: v = relu(rs*(acc + u) + bias); bf16-split stores + fused column stats
    float ts[4][2], ts2[4][2];
#pragma unroll
    for (int j = 0; j < 4; j++) { ts[j][0] = ts[j][1] = ts2[j][0] = ts2[j][1] = 0.f; }
#pragma unroll
    for (int mi = 0; mi < 3; mi++) {
        int r0_ = row0 + wm + mi * 16 + (lane >> 2);
        bool ok0 = r0_ < M, ok1 = (r0_ + 8) < M;
        float d0 = 1.f, d1 = 1.f;
        if (rs) {
            if (ok0) d0 = rs[r0_];
            if (ok1) d1 = rs[r0_ + 8];
        }
#pragma unroll
        for (int j = 0; j < 4; j++) {
            int gc = col0 + wn + (j >> 1) * 16 + (j & 1) * 8 + (lane & 3) * 2;
            float bv0 = bias[gc], bv1 = bias[gc + 1];
            float u0 = prebias ? prebias[gc] : 0.f;
            float u1 = prebias ? prebias[gc + 1] : 0.f;
            float v0 = d0 * (acc[mi][j][0] + u0) + bv0; v0 = v0 > 0.f ? v0 : 0.f;
            float v1 = d0 * (acc[mi][j][1] + u1) + bv1; v1 = v1 > 0.f ? v1 : 0.f;
            float v2 = d1 * (acc[mi][j][2] + u0) + bv0; v2 = v2 > 0.f ? v2 : 0.f;
            float v3 = d1 * (acc[mi][j][3] + u1) + bv1; v3 = v3 > 0.f ? v3 : 0.f;
            if (ok0) { ts[j][0] += v0; ts2[j][0] += v0 * v0;
                       ts[j][1] += v1; ts2[j][1] += v1 * v1; }
            if (ok1) { ts[j][0] += v2; ts2[j][0] += v2 * v2;
                       ts[j][1] += v3; ts2[j][1] += v3 * v3; }
            unsigned short h0, h1_, h2_, h3_, l0, l1_, l2_, l3_;
            bsplit(v0, h0, l0); bsplit(v1, h1_, l1_);
            bsplit(v2, h2_, l2_); bsplit(v3, h3_, l3_);
            if (ok0) {
                *(uint32_t*)&Ch[(size_t)r0_ * Ncols + gc] = (uint32_t)h0 | ((uint32_t)h1_ << 16);
                *(uint32_t*)&Cl[(size_t)r0_ * Ncols + gc] = (uint32_t)l0 | ((uint32_t)l1_ << 16);
            }
            if (ok1) {
                *(uint32_t*)&Ch[(size_t)(r0_ + 8) * Ncols + gc] = (uint32_t)h2_ | ((uint32_t)h3_ << 16);
                *(uint32_t*)&Cl[(size_t)(r0_ + 8) * Ncols + gc] = (uint32_t)l2_ | ((uint32_t)l3_ << 16);
            }
        }
    }

    // warp-level stat reduce
#pragma unroll
    for (int j = 0; j < 4; j++)
#pragma unroll
        for (int k = 0; k < 2; k++) {
#pragma unroll
            for (int off = 4; off < 32; off <<= 1) {
                ts[j][k] += __shfl_xor_sync(0xffffffffu, ts[j][k], off);
                ts2[j][k] += __shfl_xor_sync(0xffffffffu, ts2[j][k], off);
            }
        }
    float* sS = (float*)sb;                 // [12][32]
    float* sS2 = sS + 12 * 32;
    __syncthreads();
    if (lane < 4) {
#pragma unroll
        for (int j = 0; j < 4; j++) {
            int cloc = (j >> 1) * 16 + (j & 1) * 8 + lane * 2;
            sS[wid * 32 + cloc] = ts[j][0];
            sS[wid * 32 + cloc + 1] = ts[j][1];
            sS2[wid * 32 + cloc] = ts2[j][0];
            sS2[wid * 32 + cloc + 1] = ts2[j][1];
        }
    }
    __syncthreads();
    if (tid < 128) {
        int c = tid;
        int g = c >> 5, cloc = c & 31;
        float s = 0.f, s2 = 0.f;
#pragma unroll
        for (int w = 0; w < 3; w++) {
            s += sS[(g + 4 * w) * 32 + cloc];
            s2 += sS2[(g + 4 * w) * 32 + cloc];
        }
        g_psum[blockIdx.y * 256 + col0 + c] = s;
        g_psum2[blockIdx.y * 256 + col0 + c] = s2;
        __threadfence();
    }
    __syncthreads();

    // ---- grid-resident handoff: last CTA finalizes stats + releases flag ----
    __shared__ int s_last;
    if (tid == 0) {
        unsigned int o = atomicAdd(&g_ctr, 1u);
        s_last = (o == TOTAL_CTAS - 1) ? 1 : 0;
    }
    __syncthreads();
    if (s_last) {
        __threadfence();
        if (tid < 256) {
            int c = tid;
            float s = 0.f, s2 = 0.f;
            for (int b = 0; b < NBY; b++) { s += g_psum[b * 256 + c]; s2 += g_psum2[b * 256 + c]; }
            float m = s / (float)M;
            float var = s2 / (float)M - m * m;
            g_mean[c] = m;
            g_rstd[c] = rsqrtf(var + 1e-5f);
        }
        if (tid == 0) g_ctr = 0;
        __threadfence();
        __syncthreads();
        if (tid == 0) atomicExch(&g_flag, gen);
    } else {
        if (tid == 0) {
            while (atomicAdd(&g_flag, 0u) < gen) __nanosleep(64);
        }
        __syncthreads();
        __threadfence();
    }

    // ---- cooperative BN fold ----
    {
        const int Kn = 256, ntk = 8;
        int ntiles = ntk * (Nn >> 5);
        int ngemv = Nn >> 5;
        int unit = blockIdx.y * 2 + blockIdx.x;   // 0..139
        if (unit < ntiles) {
            __shared__ float t[32][33];
            __shared__ float ss[32];
            int k0 = (unit % ntk) * 32, n0 = (unit / ntk) * 32;
            int tx = tid & 31, ty = tid >> 5;
            if (tid < 32) ss[tid] = g_rstd[k0 + tid] * gamn[k0 + tid];
            for (int dy = ty; dy < 32; dy += 12)
                t[dy][tx] = Wn[(size_t)(k0 + dy) * Nn + n0 + tx];
            __syncthreads();
            for (int dy = ty; dy < 32; dy += 12) {
                int n = n0 + dy, k = k0 + tx;
                unsigned short h, l;
                bsplit(t[tx][dy] * ss[tx], h, l);
                tho[(size_t)n * Kn + k] = __ushort_as_bfloat16(h);
                tlo[(size_t)n * Kn + k] = __ushort_as_bfloat16(l);
            }
        } else if (unit < ntiles + ngemv) {
            int n0 = (unit - ntiles) * 32;
            int tx = tid & 31, ty = tid >> 5;
            __shared__ float tsv[256];
            __shared__ float red[8][33];
            if (tid < 256) {
                float s = g_rstd[tid] * gamn[tid];
                tsv[tid] = betn[tid] - g_mean[tid] * s;
            }
            __syncthreads();
            if (ty < 8) {
                int kbeg = ty * 32;
                float w[32];
#pragma unroll
                for (int i = 0; i < 32; i++)
                    w[i] = Wn[(size_t)(kbeg + i) * Nn + n0 + tx];
                float acc2 = 0.f;
#pragma unroll
                for (int i = 0; i < 32; i++) acc2 += tsv[kbeg + i] * w[i];
                red[ty][tx] = acc2;
            }
            __syncthreads();
            if (ty == 0) {
                float s = red[0][tx];
#pragma unroll
                for (int y = 1; y < 8; y++) s += red[y][tx];
                if (extran) s += extran[n0 + tx];
                uo[n0 + tx] = s;
            }
        }
    }
}

// ---------------- fused fc0+fc1: BM=80, 320 threads (10 warps), grid 125 (single wave) ----
// Stage1: 80x128 tile, K=256, warp tile 16x64 (5m x 2n). Stage2: warp (g,p): rows g*16..+16,
// cols p*32..+32 of the 40-wide output.
#define F_A_H 0
#define F_A_L 6400
#define F_B_H 12800
#define F_B_L 23040
#define F_BUF 33280
#define FSMEM (3 * F_BUF + 1024)

__global__ void __launch_bounds__(320, 1)
fused_fc(const __nv_bfloat16* __restrict__ Ah, const __nv_bfloat16* __restrict__ Al,
         const __nv_bfloat16* __restrict__ Bh, const __nv_bfloat16* __restrict__ Bl,
         const float* __restrict__ bias0,
         const __nv_bfloat16* __restrict__ W3h, const __nv_bfloat16* __restrict__ W3l,
         const float* __restrict__ bias1, float* __restrict__ Out, int M) {
    extern __shared__ char smraw[];
    uint32_t raw = s2u(smraw);
    uint32_t sbase = (raw + 1023u) & ~1023u;

    const int tid = threadIdx.x, lane = tid & 31, wid = tid >> 5;
    const int row0 = blockIdx.y * 80;
    const int wm = (wid >> 1) * 16, wnp = (wid & 1);  // stage1: n-half = wnp*64
    const int Kpad = 256, nch = 8;

    float acc[8][4];
#pragma unroll
    for (int j = 0; j < 8; j++)
#pragma unroll
        for (int c = 0; c < 4; c++) acc[j][c] = 0.f;

    const uint32_t a_lo = (uint32_t)((lane & 15) * ROWB + ((lane >> 4) & 1) * 16);
    const uint32_t b_lo = (uint32_t)((lane & 7) * ROWB + ((lane & 16) ? 8 * ROWB : 0) +
                                     ((lane & 8) ? 16 : 0));

    auto prefetch = [&](int ch) {
        const uint32_t bu = sbase + (ch % 3) * F_BUF;
        const int k0 = ch << 5;
        {   // A: 80 rows x 4 x 16B = 320 units (one per thread)
            int r = tid >> 2, q = tid & 3;
            size_t ao = (size_t)(row0 + r) * Kpad + k0 + q * 8;
            uint32_t so = (uint32_t)(r * ROWB + q * 16);
            CP_ASYNC16(bu + F_A_H + so, (const void*)(Ah + ao));
            CP_ASYNC16(bu + F_A_L + so, (const void*)(Al + ao));
        }
        for (int idx = tid; idx < 512; idx += 320) {  // B: 128 rows x 4
            int r = idx >> 2, q = idx & 3;
            size_t bo = (size_t)r * Kpad + k0 + q * 8;
            uint32_t so = (uint32_t)(r * ROWB + q * 16);
            CP_ASYNC16(bu + F_B_H + so, (const void*)(Bh + bo));
            CP_ASYNC16(bu + F_B_L + so, (const void*)(Bl + bo));
        }
        asm volatile("cp.async.commit_group;" ::: "memory");
    };

    prefetch(0);
    prefetch(1);

    for (int ch = 0; ch < nch; ch++) {
        if (ch + 1 < nch) { asm volatile("cp.async.wait_group 1;" ::: "memory"); }
        else              { asm volatile("cp.async.wait_group 0;" ::: "memory"); }
        __syncthreads();
        if (ch + 2 < nch) prefetch(ch + 2);

        const uint32_t bufu = sbase + (ch % 3) * F_BUF;
#pragma unroll
        for (int ks = 0; ks < 2; ks++) {
            uint32_t ka = bufu + F_A_H + (uint32_t)(wm * ROWB) + a_lo + ks * 32;
            uint32_t ah[4], al[4];
            LDX4(ah, ka);
            LDX4(al, ka + (F_A_L - F_A_H));
#pragma unroll
            for (int nt = 0; nt < 4; nt++) {
                uint32_t kb = bufu + F_B_H + (uint32_t)((wnp * 64 + nt * 16) * ROWB) + b_lo + ks * 32;
                uint32_t bh[4], bl[4];
                LDX4(bh, kb);
                LDX4(bl, kb + (F_B_L - F_B_H));
                MMA(acc[nt * 2 + 0], ah, bh[0], bh[1]);
                MMA(acc[nt * 2 + 1], ah, bh[2], bh[3]);
                MMA(acc[nt * 2 + 0], al, bh[0], bh[1]);
                MMA(acc[nt * 2 + 1], al, bh[2], bh[3]);
                MMA(acc[nt * 2 + 0], ah, bl[0], bl[1]);
                MMA(acc[nt * 2 + 1], ah, bl[2], bl[3]);
            }
        }
        __syncthreads();
    }
    __syncthreads();  // stage-1 buffers now free

    // SA: 4 chunks x (hi 6400 + lo 6400) = 51200; SB at +51200: 4 chunks x (hi 5120 + lo 5120)
    const uint32_t SA = sbase;
    const uint32_t SB = sbase + 51200;

    // load fc1 weights (64 n-rows x 128 k, chunked by 32 k)
    for (int idx = tid; idx < 1024; idx += 320) {
        int c = idx >> 8, r = (idx >> 2) & 63, q = idx & 3;
        size_t go = (size_t)r * 128 + c * 32 + q * 8;
        uint32_t so = SB + c * 10240 + (uint32_t)(r * ROWB + q * 16);
        CP_ASYNC16(so, (const void*)(W3h + go));
        CP_ASYNC16(so + 5120, (const void*)(W3l + go));
    }
    asm volatile("cp.async.commit_group;" ::: "memory");

    // stage-1 epilogue: relu(acc+bias0) -> bf16 split into SA (chunked layout)
    char* sac = smraw + (sbase - raw);
    {
        int rl = wm + (lane >> 2);
#pragma unroll
        for (int n8 = 0; n8 < 8; n8++) {
            int cl = wnp * 64 + n8 * 8 + (lane & 3) * 2;
            float bv0 = bias0[cl], bv1 = bias0[cl + 1];
            float v0 = acc[n8][0] + bv0; v0 = v0 > 0.f ? v0 : 0.f;
            float v1 = acc[n8][1] + bv1; v1 = v1 > 0.f ? v1 : 0.f;
            float v2 = acc[n8][2] + bv0; v2 = v2 > 0.f ? v2 : 0.f;
            float v3 = acc[n8][3] + bv1; v3 = v3 > 0.f ? v3 : 0.f;
            unsigned short h0, h1, h2, h3, l0, l1, l2, l3;
            bsplit(v0, h0, l0); bsplit(v1, h1, l1);
            bsplit(v2, h2, l2); bsplit(v3, h3, l3);
            uint32_t off = (uint32_t)((cl >> 5) * 12800 + rl * ROWB + (cl & 31) * 2);
            *(uint32_t*)(sac + off) = (uint32_t)h0 | ((uint32_t)h1 << 16);
            *(uint32_t*)(sac + off + 6400) = (uint32_t)l0 | ((uint32_t)l1 << 16);
            uint32_t off8 = off + 8 * ROWB;
            *(uint32_t*)(sac + off8) = (uint32_t)h2 | ((uint32_t)h3 << 16);
            *(uint32_t*)(sac + off8 + 6400) = (uint32_t)l2 | ((uint32_t)l3 << 16);
        }
    }
    asm volatile("cp.async.wait_group 0;" ::: "memory");
    __syncthreads();

    // stage 2: warp (g = wid>>1, p = wid&1): rows g*16..+16, B row groups p*2..p*2+2
    const int g = wid >> 1, p = wid & 1;
    float acc2[4][4];
#pragma unroll
    for (int j = 0; j < 4; j++)
#pragma unroll
        for (int c = 0; c < 4; c++) acc2[j][c] = 0.f;

#pragma unroll
    for (int c = 0; c < 4; c++) {
#pragma unroll
        for (int ks = 0; ks < 2; ks++) {
            uint32_t ka = SA + c * 12800 + (uint32_t)(g * 16 * ROWB) + a_lo + ks * 32;
            uint32_t ah[4], al[4];
            LDX4(ah, ka);
            LDX4(al, ka + 6400);
#pragma unroll
            for (int ntl = 0; ntl < 2; ntl++) {
                int nt = p * 2 + ntl;
                uint32_t kb = SB + c * 10240 + (uint32_t)(nt * 16 * ROWB) + b_lo + ks * 32;
                uint32_t bh[4], bl[4];
                LDX4(bh, kb);
                LDX4(bl, kb + 5120);
                MMA(acc2[ntl * 2 + 0], ah, bh[0], bh[1]);
                MMA(acc2[ntl * 2 + 1], ah, bh[2], bh[3]);
                MMA(acc2[ntl * 2 + 0], al, bh[0], bh[1]);
                MMA(acc2[ntl * 2 + 1], al, bh[2], bh[3]);
                MMA(acc2[ntl * 2 + 0], ah, bl[0], bl[1]);
                MMA(acc2[ntl * 2 + 1], ah, bl[2], bl[3]);
            }
        }
    }

#pragma unroll
    for (int ntl = 0; ntl < 2; ntl++)
#pragma unroll
        for (int h = 0; h < 2; h++) {
            int gc = (p * 2 + ntl) * 16 + h * 8 + (lane & 3) * 2;
            if (gc >= 40) continue;
            float bv0 = bias1[gc], bv1 = bias1[gc + 1];
            int gr = row0 + g * 16 + (lane >> 2);
            float* a2 = acc2[ntl * 2 + h];
            if (gr < M) {
                float v0 = a2[0] + bv0; v0 = v0 > 0.f ? v0 : 0.f;
                float v1 = a2[1] + bv1; v1 = v1 > 0.f ? v1 : 0.f;
                *(float2*)&Out[(size_t)gr * 40 + gc] = make_float2(v0, v1);
            }
            if (gr + 8 < M) {
                float v2 = a2[2] + bv0; v2 = v2 > 0.f ? v2 : 0.f;
                float v3 = a2[3] + bv1; v3 = v3 > 0.f ? v3 : 0.f;
                *(float2*)&Out[(size_t)(gr + 8) * 40 + gc] = make_float2(v2, v3);
            }
        }
}

// ---------------- launch ----------------
extern "C" void kernel_launch(void* const* d_in, const int* in_sizes, int n_in,
                              void* d_out, int out_size) {
    const float* x   = (const float*)d_in[0];
    const void*  ei  = d_in[1];
    const float* W0  = (const float*)d_in[2];
    const float* b0  = (const float*)d_in[3];
    const float* g0  = (const float*)d_in[4];
    const float* be0 = (const float*)d_in[5];
    const float* W1  = (const float*)d_in[6];
    const float* b1  = (const float*)d_in[7];
    const float* g1  = (const float*)d_in[8];
    const float* be1 = (const float*)d_in[9];
    const float* fW0 = (const float*)d_in[10];
    const float* fb0 = (const float*)d_in[11];
    const float* fW1 = (const float*)d_in[12];
    const float* fb1 = (const float*)d_in[13];
    float* out = (float*)d_out;

    float *deg, *u1, *bias0p;
    __nv_bfloat16 *xh, *xl, *a1h, *a1l, *a2h, *a2l;
    __nv_bfloat16 *wth0, *wtl0, *wth1, *wtl1, *wth2, *wtl2, *wth3, *wtl3;
    cudaGetSymbolAddress((void**)&deg, g_deg);
    cudaGetSymbolAddress((void**)&u1, g_u1);
    cudaGetSymbolAddress((void**)&bias0p, g_bias0p);
    cudaGetSymbolAddress((void**)&xh, g_xh);
    cudaGetSymbolAddress((void**)&xl, g_xl);
    cudaGetSymbolAddress((void**)&a1h, g_a1h);
    cudaGetSymbolAddress((void**)&a1l, g_a1l);
    cudaGetSymbolAddress((void**)&a2h, g_a2h);
    cudaGetSymbolAddress((void**)&a2l, g_a2l);
    cudaGetSymbolAddress((void**)&wth0, g_wth0);
    cudaGetSymbolAddress((void**)&wtl0, g_wtl0);
    cudaGetSymbolAddress((void**)&wth1, g_wth1);
    cudaGetSymbolAddress((void**)&wtl1, g_wtl1);
    cudaGetSymbolAddress((void**)&wth2, g_wth2);
    cudaGetSymbolAddress((void**)&wtl2, g_wtl2);
    cudaGetSymbolAddress((void**)&wth3, g_wth3);
    cudaGetSymbolAddress((void**)&wtl3, g_wtl3);

    cudaFuncSetAttribute(gemm144, cudaFuncAttributeMaxDynamicSharedMemorySize, GSMEM);
    cudaFuncSetAttribute(fused_fc, cudaFuncAttributeMaxDynamicSharedMemorySize, FSMEM);

    const int M = N_NODES;

    // prep + degree
    prep_kernel<<<6208, 256>>>(W0, fW1, x, (const unsigned int*)ei);
    deg_kernel<<<(N_EDGES / 2 + 255) / 256, 256>>>(ei);

    // conv0: split(h1) = split(relu(deg.*(x@W0) + b0)); stats+finalize+fold1 fused in tail
    gemm144<<<dim3(2, NBY), 384, GSMEM>>>(xh, xl, wth0, wtl0, b0, nullptr, deg, a1h, a1l,
                                          M, 512,
                                          W1, g0, be0, wth1, wtl1, u1, nullptr, 256, 1u);

    // conv1: split(h2) = split(relu(deg.*(h1@W1' + u1) + b1)); stats+finalize+fold2 fused
    gemm144<<<dim3(2, NBY), 384, GSMEM>>>(a1h, a1l, wth1, wtl1, b1, u1, deg, a2h, a2l,
                                          M, 256,
                                          fW0, g1, be1, wth2, wtl2, bias0p, fb0, 128, 2u);

    // fused fc0+fc1 -> out [10000][40], 125 CTAs single wave
    fused_fc<<<dim3(1, 125), 320, FSMEM>>>(a2h, a2l, wth2, wtl2, bias0p, wth3, wtl3, fb1, out, M);
}